// round 14
// baseline (speedup 1.0000x reference)
#include <cuda_runtime.h>
#include <cuda_fp16.h>
#include <cstdint>

#define NR 8192
#define DC 1024
#define CCAP 2048                    // candidate capacity per row
#define SCR_MARGIN 22.0f             // screening threshold below approx max

// int8 scales (validated R10-R13)
#define S8_HI 32.0f
#define S8_LO 65536.0f
#define SIN_HI 16.0f
#define SIN_LO 16384.0f
#define SW_HI  1024.0f
#define SW_LO  1048576.0f
#define SCOMB_PROJ (1.0f / 16777216.0f)    // 2^-24
#define SCOMB_SCR  (1.0f / 1024.0f)        // (1/32)^2 screening

// ---------------------------------------------------------------------------
// Static device scratch. Split-fp16 tensors stored [rows, 2K]: hi | lo.
// ---------------------------------------------------------------------------
__device__ __half   g_Sh[(size_t)2 * NR * NR];          // approx logits fp16
__device__ __half   g_img2[(size_t)NR * 2 * DC];
__device__ __half   g_tab2[(size_t)NR * 2 * DC];
__device__ int8_t   g_in8[(size_t)2 * NR * 2 * DC];
__device__ __half   g_w2[(size_t)6 * DC * 2 * DC];
__device__ int8_t   g_w8[(size_t)6 * DC * 2 * DC];
__device__ __half   g_wo2[(size_t)2 * DC * 4 * DC];
__device__ __half   g_qk2[(size_t)4 * NR * 2 * DC];     // q1,k1,q2,k2 fp16 hi|lo
__device__ int8_t   g_qk8[(size_t)4 * NR * 2 * DC];     // q1,k1,q2,k2 int8 hi|lo
__device__ __half   g_v2[(size_t)2 * NR * 2 * DC];      // v1,v2 row-major hi|lo
__device__ unsigned g_rmax[2 * NR];                     // ordered-uint row maxes
__device__ int      g_Pidx[(size_t)2 * NR * CCAP];
__device__ float    g_Pval[(size_t)2 * NR * CCAP];
__device__ int      g_Pcnt[2 * NR];
__device__ __half   g_fused2[(size_t)NR * 4 * DC];

// ---------------------------------------------------------------------------
// helpers
// ---------------------------------------------------------------------------
__device__ __forceinline__ uint32_t smem_u32(const void* p) {
    uint32_t a;
    asm("{ .reg .u64 t; cvta.to.shared.u64 t, %1; cvt.u32.u64 %0, t; }" : "=r"(a) : "l"(p));
    return a;
}
__device__ __forceinline__ void cp16(uint32_t d, const void* g) {
    asm volatile("cp.async.cg.shared.global [%0], [%1], 16;"
                 :: "r"(d), "l"(__cvta_generic_to_global(g)) : "memory");
}
__device__ __forceinline__ void ldm4(uint32_t* r, uint32_t a) {
    asm volatile("ldmatrix.sync.aligned.m8n8.x4.shared.b16 {%0,%1,%2,%3}, [%4];"
                 : "=r"(r[0]), "=r"(r[1]), "=r"(r[2]), "=r"(r[3]) : "r"(a));
}
__device__ __forceinline__ void mma16816(float* d, const uint32_t* a, const uint32_t* b) {
    asm("mma.sync.aligned.m16n8k16.row.col.f32.f16.f16.f32 "
        "{%0,%1,%2,%3}, {%4,%5,%6,%7}, {%8,%9}, {%0,%1,%2,%3};"
        : "+f"(d[0]), "+f"(d[1]), "+f"(d[2]), "+f"(d[3])
        : "r"(a[0]), "r"(a[1]), "r"(a[2]), "r"(a[3]), "r"(b[0]), "r"(b[1]));
}
__device__ __forceinline__ void mma16832s8(int* d, const uint32_t* a, const uint32_t* b) {
    asm("mma.sync.aligned.m16n8k32.row.col.s32.s8.s8.s32 "
        "{%0,%1,%2,%3}, {%4,%5,%6,%7}, {%8,%9}, {%0,%1,%2,%3};"
        : "+r"(d[0]), "+r"(d[1]), "+r"(d[2]), "+r"(d[3])
        : "r"(a[0]), "r"(a[1]), "r"(a[2]), "r"(a[3]), "r"(b[0]), "r"(b[1]));
}
__device__ __forceinline__ __half2 split_hi(float x0, float x1, __half2& lo) {
    __half h0 = __float2half_rn(x0), h1 = __float2half_rn(x1);
    lo = __halves2half2(__float2half_rn(x0 - __half2float(h0)),
                        __float2half_rn(x1 - __half2float(h1)));
    return __halves2half2(h0, h1);
}
__device__ __forceinline__ int8_t q8clamp(float x, float s) {
    int v = __float2int_rn(x * s);
    v = v > 127 ? 127 : (v < -127 ? -127 : v);
    return (int8_t)v;
}
// ordered-uint encoding for float atomicMax (monotone; 0 < key(-inf))
__device__ __forceinline__ unsigned fkey(float x) {
    unsigned b = __float_as_uint(x);
    return (b & 0x80000000u) ? ~b : (b | 0x80000000u);
}
__device__ __forceinline__ float fdec(unsigned u) {
    return (u & 0x80000000u) ? __uint_as_float(u ^ 0x80000000u) : __uint_as_float(~u);
}

// ---------------------------------------------------------------------------
// Batched split NT GEMM:  C = A . B^T per blockIdx.z
// PASSES=4: int8 corrections (2 sweeps) + fp16 hi·hi (fp32 acc)
// PASSES=8: SCREEN — int8 hi·hi only; OUT_MODE=2 writes fp16 + row-max atomics
// PASSES=1: fp16 hi·hi only.
// OUT_MODE: 0 = fp32 to Cf, 1 = split fp16 to Ch, 2 = plain fp16 + rowmax.
// ---------------------------------------------------------------------------
#define TPB 256
#define AST 144
#define STG (128 * AST * 2)
#define GSMEM (3 * STG)

struct GB { const __half* A; const __half* B; const int8_t* A8; const int8_t* B8;
            const float* bias; float* Cf; __half* Ch; int8_t* C8; unsigned* rmax; };
struct GB4 { GB g[4]; };

template <int OUT_MODE, int BIAS, int PASSES, int EMIT8>
__global__ __launch_bounds__(TPB, 2)
void hgemm3(const __grid_constant__ GB4 batch, int K,
            size_t ldA, size_t ldB, size_t ld8, int ldc, int lo_off, float s_comb)
{
    extern __shared__ char smc[];
    const uint32_t sb = smem_u32(smc);
    const GB gb = batch.g[blockIdx.z];
    const int tid = threadIdx.x;
    const int wid = tid >> 5, lane = tid & 31;
    const int g = lane >> 2, t = lane & 3;
    const int wm = wid & 1, wn = wid >> 1;
    const int m0 = blockIdx.y * 128, n0 = blockIdx.x * 128;

    const int K64 = K >> 6;
    const int corr  = (PASSES == 4) ? K64 : ((PASSES == 8) ? (K >> 7) : 0);
    const int total = (PASSES == 8) ? corr : corr + K64;

    const int lr = tid >> 3;
    const int lc  = (tid & 7) * 8;
    const int lcB = (tid & 7) * 16;

    auto load_stage = [&](int s, int step) {
        if (step < total) {
            const uint32_t da = sb + s * STG + lr * AST + lcB;
            const uint32_t db = da + 128 * AST;
            if ((PASSES == 4 || PASSES == 8) && step < corr) {
                int a8o, b8o, kk;
                if (PASSES == 8) { a8o = 0; b8o = 0; kk = step; }
                else {
                    const int spw = K >> 7;
                    const int swp = step / spw;
                    kk = step - swp * spw;
                    a8o = swp ? K : 0;
                    b8o = swp ? 0 : K;
                }
                const int8_t* ga  = gb.A8 + (size_t)(m0 + lr) * ld8 + a8o + kk * 128 + lcB;
                const int8_t* gbp = gb.B8 + (size_t)(n0 + lr) * ld8 + b8o + kk * 128 + lcB;
#pragma unroll
                for (int i = 0; i < 4; ++i) {
                    cp16(da + i * 32 * AST, ga  + (size_t)i * 32 * ld8);
                    cp16(db + i * 32 * AST, gbp + (size_t)i * 32 * ld8);
                }
            } else {
                const int kk = step - corr;
                const __half* ga  = gb.A + (size_t)(m0 + lr) * ldA + (size_t)kk * 64 + lc;
                const __half* gbp = gb.B + (size_t)(n0 + lr) * ldB + (size_t)kk * 64 + lc;
#pragma unroll
                for (int i = 0; i < 4; ++i) {
                    cp16(da + i * 32 * AST, ga  + (size_t)i * 32 * ldA);
                    cp16(db + i * 32 * AST, gbp + (size_t)i * 32 * ldB);
                }
            }
        }
        asm volatile("cp.async.commit_group;" ::: "memory");
    };

    const uint32_t aoff = (uint32_t)(wm * 64 + (lane & 15)) * AST + ((lane >> 4) << 4);
    const uint32_t boff = 128 * AST +
        (uint32_t)(wn * 32 + ((lane & 7) | ((lane >> 1) & 8))) * AST +
        (((lane >> 3) & 1) << 4);

    load_stage(0, 0);
    load_stage(1, 1);

    int iacc[4][4][4];
    if (PASSES == 4 || PASSES == 8) {
#pragma unroll
        for (int i = 0; i < 4; ++i)
#pragma unroll
            for (int j = 0; j < 4; ++j)
#pragma unroll
                for (int r = 0; r < 4; ++r) iacc[i][j][r] = 0;
    }

    for (int step = 0; step < corr; ++step) {
        asm volatile("cp.async.wait_group 1;" ::: "memory");
        __syncthreads();
        load_stage((step + 2) % 3, step + 2);
        const uint32_t sbase = sb + (step % 3) * STG;
#pragma unroll
        for (int kh = 0; kh < 4; ++kh) {
            const uint32_t ko = kh * 32;
            uint32_t af[4][4], bf[4][2];
#pragma unroll
            for (int mt = 0; mt < 4; ++mt)
                ldm4(af[mt], sbase + aoff + (uint32_t)mt * 16 * AST + ko);
#pragma unroll
            for (int np = 0; np < 2; ++np) {
                uint32_t r[4];
                ldm4(r, sbase + boff + (uint32_t)np * 16 * AST + ko);
                bf[np * 2][0] = r[0];      bf[np * 2][1] = r[1];
                bf[np * 2 + 1][0] = r[2];  bf[np * 2 + 1][1] = r[3];
            }
#pragma unroll
            for (int mt = 0; mt < 4; ++mt)
#pragma unroll
                for (int nt = 0; nt < 4; ++nt)
                    mma16832s8(iacc[mt][nt], af[mt], bf[nt]);
        }
    }

    float acc[4][4][4];
#pragma unroll
    for (int i = 0; i < 4; ++i)
#pragma unroll
        for (int j = 0; j < 4; ++j) {
            if (PASSES == 4 || PASSES == 8) {
#pragma unroll
                for (int r = 0; r < 4; ++r)
                    acc[i][j][r] = (float)iacc[i][j][r] * s_comb;
            } else {
#pragma unroll
                for (int r = 0; r < 4; ++r) acc[i][j][r] = 0.0f;
            }
        }

    for (int step = corr; step < total; ++step) {
        asm volatile("cp.async.wait_group 1;" ::: "memory");
        __syncthreads();
        load_stage((step + 2) % 3, step + 2);
        const uint32_t sbase = sb + (step % 3) * STG;
#pragma unroll
        for (int kh = 0; kh < 4; ++kh) {
            const uint32_t ko = kh * 32;
            uint32_t af[4][4], bf[4][2];
#pragma unroll
            for (int mt = 0; mt < 4; ++mt)
                ldm4(af[mt], sbase + aoff + (uint32_t)mt * 16 * AST + ko);
#pragma unroll
            for (int np = 0; np < 2; ++np) {
                uint32_t r[4];
                ldm4(r, sbase + boff + (uint32_t)np * 16 * AST + ko);
                bf[np * 2][0] = r[0];      bf[np * 2][1] = r[1];
                bf[np * 2 + 1][0] = r[2];  bf[np * 2 + 1][1] = r[3];
            }
#pragma unroll
            for (int mt = 0; mt < 4; ++mt)
#pragma unroll
                for (int nt = 0; nt < 4; ++nt)
                    mma16816(acc[mt][nt], af[mt], bf[nt]);
        }
    }

    // ---- rowmax smem init (screening mode) ----
    unsigned* rm = reinterpret_cast<unsigned*>(smc);
    if (OUT_MODE == 2) {
        __syncthreads();                       // all smem reads done
        if (tid < 128) rm[tid] = 0u;
        __syncthreads();
    }

    // ---- epilogue ----
#pragma unroll
    for (int mt = 0; mt < 4; ++mt) {
        const int r0 = m0 + wm * 64 + mt * 16 + g;
        const int r1 = r0 + 8;
#pragma unroll
        for (int nt = 0; nt < 4; ++nt) {
            const int col = n0 + wn * 32 + nt * 8 + 2 * t;
            float v00 = acc[mt][nt][0], v01 = acc[mt][nt][1];
            float v10 = acc[mt][nt][2], v11 = acc[mt][nt][3];
            if (BIAS == 1) {
                const float b0 = gb.bias[col], b1 = gb.bias[col + 1];
                v00 += b0; v01 += b1; v10 += b0; v11 += b1;
            } else if (BIAS == 2) {
                const float b0 = gb.bias[r0], b1 = gb.bias[r1];
                v00 += b0; v01 += b0; v10 += b1; v11 += b1;
            }
            if (OUT_MODE == 0) {
                *reinterpret_cast<float2*>(&gb.Cf[(size_t)r0 * ldc + col]) = make_float2(v00, v01);
                *reinterpret_cast<float2*>(&gb.Cf[(size_t)r1 * ldc + col]) = make_float2(v10, v11);
            } else if (OUT_MODE == 2) {
                *reinterpret_cast<__half2*>(&gb.Ch[(size_t)r0 * ldc + col]) =
                    __floats2half2_rn(v00, v01);
                *reinterpret_cast<__half2*>(&gb.Ch[(size_t)r1 * ldc + col]) =
                    __floats2half2_rn(v10, v11);
                atomicMax(&rm[wm * 64 + mt * 16 + g],     fkey(fmaxf(v00, v01)));
                atomicMax(&rm[wm * 64 + mt * 16 + g + 8], fkey(fmaxf(v10, v11)));
            } else {
                __half2 lo0, lo1;
                __half2 hi0 = split_hi(v00, v01, lo0);
                __half2 hi1 = split_hi(v10, v11, lo1);
                __half2* p0 = reinterpret_cast<__half2*>(&gb.Ch[(size_t)r0 * ldc + col]);
                __half2* p1 = reinterpret_cast<__half2*>(&gb.Ch[(size_t)r1 * ldc + col]);
                p0[0] = hi0;  p0[lo_off / 2] = lo0;
                p1[0] = hi1;  p1[lo_off / 2] = lo1;
                if (EMIT8) {
                    const float l00 = __low2float(lo0), l01 = __high2float(lo0);
                    const float l10 = __low2float(lo1), l11 = __high2float(lo1);
                    char2 h8a = { q8clamp(v00, S8_HI), q8clamp(v01, S8_HI) };
                    char2 h8b = { q8clamp(v10, S8_HI), q8clamp(v11, S8_HI) };
                    char2 l8a = { q8clamp(l00, S8_LO), q8clamp(l01, S8_LO) };
                    char2 l8b = { q8clamp(l10, S8_LO), q8clamp(l11, S8_LO) };
                    *reinterpret_cast<char2*>(&gb.C8[(size_t)r0 * ldc + col])          = h8a;
                    *reinterpret_cast<char2*>(&gb.C8[(size_t)r1 * ldc + col])          = h8b;
                    *reinterpret_cast<char2*>(&gb.C8[(size_t)r0 * ldc + lo_off + col]) = l8a;
                    *reinterpret_cast<char2*>(&gb.C8[(size_t)r1 * ldc + lo_off + col]) = l8b;
                }
            }
        }
    }

    if (OUT_MODE == 2) {
        __syncthreads();
        if (tid < 128) atomicMax(&gb.rmax[m0 + tid], rm[tid]);
    }
}

// ---------------------------------------------------------------------------
// fp32 [R,C] -> split fp16 [R,2C] + int8 [R,2C]
// ---------------------------------------------------------------------------
__global__ __launch_bounds__(256)
void convert_split(const float* __restrict__ in, __half* __restrict__ out,
                   int8_t* __restrict__ out8, int C, size_t total)
{
    size_t i = ((size_t)blockIdx.x * 256 + threadIdx.x) * 4;
    if (i >= total) return;
    float4 v = *reinterpret_cast<const float4*>(&in[i]);
    size_t r = i / C;
    int c = (int)(i - r * C);
    __half2 lo0, lo1;
    __half2 hi0 = split_hi(v.x, v.y, lo0);
    __half2 hi1 = split_hi(v.z, v.w, lo1);
    __half* row = out + r * (2 * (size_t)C);
    *reinterpret_cast<__half2*>(&row[c])         = hi0;
    *reinterpret_cast<__half2*>(&row[c + 2])     = hi1;
    *reinterpret_cast<__half2*>(&row[C + c])     = lo0;
    *reinterpret_cast<__half2*>(&row[C + c + 2]) = lo1;
    int8_t* row8 = out8 + r * (2 * (size_t)C);
    char4 h8 = { q8clamp(__low2float(hi0), SIN_HI), q8clamp(__high2float(hi0), SIN_HI),
                 q8clamp(__low2float(hi1), SIN_HI), q8clamp(__high2float(hi1), SIN_HI) };
    char4 l8 = { q8clamp(__low2float(lo0), SIN_LO), q8clamp(__high2float(lo0), SIN_LO),
                 q8clamp(__low2float(lo1), SIN_LO), q8clamp(__high2float(lo1), SIN_LO) };
    *reinterpret_cast<char4*>(&row8[c])     = h8;
    *reinterpret_cast<char4*>(&row8[C + c]) = l8;
}

// ---------------------------------------------------------------------------
// All 7 weight transposes in ONE launch (+ int8 for projection weights)
// ---------------------------------------------------------------------------
__global__ __launch_bounds__(256)
void weight_prep(const float* w0, const float* w1, const float* w2c,
                 const float* w3, const float* w4, const float* w5,
                 const float* w6,
                 __half* o0, __half* o1, __half* o2, __half* o3,
                 __half* o4, __half* o5, __half* o6, int8_t* o8base)
{
    const float* src; __half* dst; int R, C;
    switch (blockIdx.z) {
        case 0: src = w0; dst = o0; R = DC; C = DC; break;
        case 1: src = w1; dst = o1; R = DC; C = DC; break;
        case 2: src = w2c; dst = o2; R = DC; C = DC; break;
        case 3: src = w3; dst = o3; R = DC; C = DC; break;
        case 4: src = w4; dst = o4; R = DC; C = DC; break;
        case 5: src = w5; dst = o5; R = DC; C = DC; break;
        default: src = w6; dst = o6; R = 2 * DC; C = 2 * DC; break;
    }
    const int bx = blockIdx.x * 32, by = blockIdx.y * 32;
    if (bx >= C || by >= R) return;
    int8_t* dst8 = (blockIdx.z < 6)
        ? o8base + (size_t)blockIdx.z * DC * 2 * DC : nullptr;

    __shared__ float tl[32][33];
    const int tx = threadIdx.x, ty = threadIdx.y;
#pragma unroll
    for (int j = ty; j < 32; j += 8)
        tl[j][tx] = src[(size_t)(by + j) * C + bx + tx];
    __syncthreads();
#pragma unroll
    for (int j = ty; j < 32; j += 8) {
        const float v = tl[tx][j];
        const __half h = __float2half_rn(v);
        const float hf = __half2float(h);
        const __half l = __float2half_rn(v - hf);
        __half* row = dst + (size_t)(bx + j) * (2 * (size_t)R);
        row[by + tx]     = h;
        row[R + by + tx] = l;
        if (dst8) {
            int8_t* row8 = dst8 + (size_t)(bx + j) * (2 * (size_t)R);
            row8[by + tx]     = q8clamp(hf, SW_HI);
            row8[R + by + tx] = q8clamp(__half2float(l), SW_LO);
        }
    }
}

// ---------------------------------------------------------------------------
// Candidate selection (pure streaming): one block per (row, branch).
// thr from precomputed rowmax; in-order compaction; writes Pidx/Pcnt.
// ---------------------------------------------------------------------------
__global__ __launch_bounds__(256)
void select_candidates(const __half* __restrict__ Sh,
                       const unsigned* __restrict__ rmax,
                       int* __restrict__ Pidx, int* __restrict__ Pcnt)
{
    __shared__ int scn[256];
    __shared__ int lidx[CCAP];
    __shared__ int ltot;

    const int rowi = blockIdx.x, br = blockIdx.y;
    const int tid = threadIdx.x;
    const __half* ap = Sh + ((size_t)br * NR + rowi) * NR;
    const float thr = fdec(rmax[br * NR + rowi]) - SCR_MARGIN;
    if (tid == 0) ltot = 0;
    __syncthreads();

    for (int base = 0; base < NR; base += 1024) {
        const int i4 = base + tid * 4;
        __half2 h0 = *reinterpret_cast<const __half2*>(&ap[i4]);
        __half2 h1 = *reinterpret_cast<const __half2*>(&ap[i4 + 2]);
        float a0 = __low2float(h0), a1 = __high2float(h0);
        float a2 = __low2float(h1), a3 = __high2float(h1);
        int c = (a0 > thr) + (a1 > thr) + (a2 > thr) + (a3 > thr);
        scn[tid] = c;
        __syncthreads();
#pragma unroll
        for (int s = 1; s < 256; s <<= 1) {
            int add = (tid >= s) ? scn[tid - s] : 0;
            __syncthreads();
            scn[tid] += add;
            __syncthreads();
        }
        int o = ltot + scn[tid] - c;
        const int chunk_total = scn[255];
        float av[4] = { a0, a1, a2, a3 };
#pragma unroll
        for (int e = 0; e < 4; ++e) {
            if (av[e] > thr) {
                if (o < CCAP) lidx[o] = i4 + e;
                ++o;
            }
        }
        __syncthreads();
        if (tid == 0) ltot += chunk_total;
        __syncthreads();
    }
    const int cnt = ltot < CCAP ? ltot : CCAP;
    const size_t loff = ((size_t)br * NR + rowi) * CCAP;
    for (int i = tid; i < cnt; i += 256) Pidx[loff + i] = lidx[i];
    if (tid == 0) Pcnt[br * NR + rowi] = cnt;
}

// ---------------------------------------------------------------------------
// Exact logits (gather-only, L2-friendly) + softmax over candidates.
// One block per (row, branch); warp per candidate; 16B k loads.
// ---------------------------------------------------------------------------
__global__ __launch_bounds__(256)
void exact_softmax(const __half* __restrict__ q1h, const __half* __restrict__ k1h,
                   const __half* __restrict__ q2h, const __half* __restrict__ k2h,
                   const int* __restrict__ Pidx, float* __restrict__ Pval,
                   const int* __restrict__ Pcnt)
{
    __shared__ float qs[2 * DC];      // 8 KB
    __shared__ float lcl[CCAP];       // 8 KB
    __shared__ float red[256];

    const int rowi = blockIdx.x, br = blockIdx.y;
    const int tid = threadIdx.x;
    const __half* q  = (br == 0 ? q1h : q2h) + (size_t)rowi * 2 * DC;
    const __half* kb = (br == 0 ? k1h : k2h);
    const size_t loff = ((size_t)br * NR + rowi) * CCAP;
    const int cnt = Pcnt[br * NR + rowi];

    for (int i = tid; i < DC; i += 256) {
        qs[i]      = __half2float(q[i]);
        qs[DC + i] = __half2float(q[DC + i]);
    }
    __syncthreads();

    const int wid = tid >> 5, lane = tid & 31;
    for (int c0 = wid; c0 < cnt; c0 += 8) {
        const __half* kr = kb + (size_t)__ldg(&Pidx[loff + c0]) * 2 * DC;
        float s = 0.0f;
#pragma unroll
        for (int e = lane * 8; e < DC; e += 256) {      // 4 iterations, 16B loads
            float4 h4 = *reinterpret_cast<const float4*>(&kr[e]);
            float4 l4 = *reinterpret_cast<const float4*>(&kr[DC + e]);
            const __half2* hh = reinterpret_cast<const __half2*>(&h4);
            const __half2* ll = reinterpret_cast<const __half2*>(&l4);
#pragma unroll
            for (int u = 0; u < 4; ++u) {
                const int ei = e + u * 2;
                const float kh0 = __low2float(hh[u]),  kh1 = __high2float(hh[u]);
                const float kl0 = __low2float(ll[u]),  kl1 = __high2float(ll[u]);
                s = fmaf(qs[ei],     kh0 + kl0, fmaf(qs[DC + ei],     kh0, s));
                s = fmaf(qs[ei + 1], kh1 + kl1, fmaf(qs[DC + ei + 1], kh1, s));
            }
        }
#pragma unroll
        for (int o = 16; o > 0; o >>= 1)
            s += __shfl_down_sync(0xffffffffu, s, o);
        if (lane == 0) lcl[c0] = s;
    }
    __syncthreads();

    float lmax = -3.0e38f;
    for (int i = tid; i < cnt; i += 256) lmax = fmaxf(lmax, lcl[i]);
    red[tid] = lmax;
    __syncthreads();
#pragma unroll
    for (int s = 128; s > 0; s >>= 1) {
        if (tid < s) red[tid] = fmaxf(red[tid], red[tid + s]);
        __syncthreads();
    }
    const float emax = red[0];
    __syncthreads();
    float lsum = 0.0f;
    for (int i = tid; i < cnt; i += 256) {
        const float e = __expf(lcl[i] - emax);
        lcl[i] = e;
        lsum += e;
    }
    red[tid] = lsum;
    __syncthreads();
#pragma unroll
    for (int s = 128; s > 0; s >>= 1) {
        if (tid < s) red[tid] += red[tid + s];
        __syncthreads();
    }
    const float inv = 1.0f / red[0];
    __syncthreads();
    for (int i = tid; i < cnt; i += 256) Pval[loff + i] = lcl[i] * inv;
}

// ---------------------------------------------------------------------------
// Sparse P·V (validated R12): one block per (row, branch).
// ---------------------------------------------------------------------------
__global__ __launch_bounds__(256)
void sparse_pv(const int* __restrict__ Pidx, const float* __restrict__ Pval,
               const int* __restrict__ Pcnt, const __half* __restrict__ v2,
               __half* __restrict__ fused2)
{
    __shared__ int   sidx[128];
    __shared__ float sval[128];
    const int rowi = blockIdx.x, br = blockIdx.y;
    const size_t loff = ((size_t)br * NR + rowi) * CCAP;
    const int cnt = Pcnt[br * NR + rowi];
    const __half* V = v2 + (size_t)br * NR * 2 * DC;
    const int tid = threadIdx.x;
    const int d = tid * 4;

    float a0 = 0.f, a1 = 0.f, a2 = 0.f, a3 = 0.f;
    for (int base = 0; base < cnt; base += 128) {
        const int n = min(128, cnt - base);
        if (tid < n) { sidx[tid] = Pidx[loff + base + tid]; sval[tid] = Pval[loff + base + tid]; }
        __syncthreads();
#pragma unroll 4
        for (int j = 0; j < n; ++j) {
            const float pj = sval[j];
            const __half* vr = V + (size_t)sidx[j] * (2 * DC) + d;
            const __half2 h0 = *reinterpret_cast<const __half2*>(vr);
            const __half2 h1 = *reinterpret_cast<const __half2*>(vr + 2);
            a0 = fmaf(pj, __low2float(h0), a0);
            a1 = fmaf(pj, __high2float(h0), a1);
            a2 = fmaf(pj, __low2float(h1), a2);
            a3 = fmaf(pj, __high2float(h1), a3);
        }
        __syncthreads();
    }

    const int col = (br == 0 ? DC : 0) + d;
    __half2 lo0, lo1;
    __half2 hi0 = split_hi(a0, a1, lo0);
    __half2 hi1 = split_hi(a2, a3, lo1);
    __half* frow = fused2 + (size_t)rowi * 4 * DC;
    *reinterpret_cast<__half2*>(&frow[col])              = hi0;
    *reinterpret_cast<__half2*>(&frow[col + 2])          = hi1;
    *reinterpret_cast<__half2*>(&frow[2 * DC + col])     = lo0;
    *reinterpret_cast<__half2*>(&frow[2 * DC + col + 2]) = lo1;
}

// ---------------------------------------------------------------------------
// Launch sequence
// ---------------------------------------------------------------------------
extern "C" void kernel_launch(void* const* d_in, const int* in_sizes, int n_in,
                              void* d_out, int out_size)
{
    const float* img = (const float*)d_in[0];
    const float* tab = (const float*)d_in[1];
    const float* Wqi = (const float*)d_in[2];  const float* bqi = (const float*)d_in[3];
    const float* Wkt = (const float*)d_in[4];  const float* bkt = (const float*)d_in[5];
    const float* Wvt = (const float*)d_in[6];  const float* bvt = (const float*)d_in[7];
    const float* Wqt = (const float*)d_in[8];  const float* bqt = (const float*)d_in[9];
    const float* Wki = (const float*)d_in[10]; const float* bki = (const float*)d_in[11];
    const float* Wvi = (const float*)d_in[12]; const float* bvi = (const float*)d_in[13];
    const float* Wo  = (const float*)d_in[14]; const float* bo  = (const float*)d_in[15];
    float* out = (float*)d_out;

    cudaFuncSetAttribute(hgemm3<2,0,8,0>, cudaFuncAttributeMaxDynamicSharedMemorySize, GSMEM);
    cudaFuncSetAttribute(hgemm3<0,1,1,0>, cudaFuncAttributeMaxDynamicSharedMemorySize, GSMEM);
    cudaFuncSetAttribute(hgemm3<1,1,1,0>, cudaFuncAttributeMaxDynamicSharedMemorySize, GSMEM);
    cudaFuncSetAttribute(hgemm3<1,1,4,1>, cudaFuncAttributeMaxDynamicSharedMemorySize, GSMEM);

    float *Pval;
    __half *Sh, *img2, *tab2, *w2, *wo2, *qk2, *v2, *fused2;
    int8_t *qk8, *in8, *w8;
    int *PidxP, *PcntP;
    unsigned* rmax;
    cudaGetSymbolAddress((void**)&Sh,     g_Sh);
    cudaGetSymbolAddress((void**)&img2,   g_img2);
    cudaGetSymbolAddress((void**)&tab2,   g_tab2);
    cudaGetSymbolAddress((void**)&in8,    g_in8);
    cudaGetSymbolAddress((void**)&w2,     g_w2);
    cudaGetSymbolAddress((void**)&w8,     g_w8);
    cudaGetSymbolAddress((void**)&wo2,    g_wo2);
    cudaGetSymbolAddress((void**)&qk2,    g_qk2);
    cudaGetSymbolAddress((void**)&qk8,    g_qk8);
    cudaGetSymbolAddress((void**)&v2,     g_v2);
    cudaGetSymbolAddress((void**)&rmax,   g_rmax);
    cudaGetSymbolAddress((void**)&PidxP,  g_Pidx);
    cudaGetSymbolAddress((void**)&Pval,   g_Pval);
    cudaGetSymbolAddress((void**)&PcntP,  g_Pcnt);
    cudaGetSymbolAddress((void**)&fused2, g_fused2);

    const size_t W2SZ = (size_t)DC * 2 * DC;
    __half* wqi2 = w2 + 0 * W2SZ;  __half* wkt2 = w2 + 1 * W2SZ;
    __half* wvt2 = w2 + 2 * W2SZ;  __half* wqt2 = w2 + 3 * W2SZ;
    __half* wki2 = w2 + 4 * W2SZ;  __half* wvi2 = w2 + 5 * W2SZ;
    int8_t* wqi8 = w8 + 0 * W2SZ;  int8_t* wkt8 = w8 + 1 * W2SZ;
    int8_t* wqt8 = w8 + 3 * W2SZ;  int8_t* wki8 = w8 + 4 * W2SZ;
    const size_t QK2 = (size_t)NR * 2 * DC;
    __half* q12 = qk2 + 0 * QK2;   __half* k12 = qk2 + 1 * QK2;
    __half* q22 = qk2 + 2 * QK2;   __half* k22 = qk2 + 3 * QK2;
    int8_t* q18 = qk8 + 0 * QK2;   int8_t* k18 = qk8 + 1 * QK2;
    int8_t* q28 = qk8 + 2 * QK2;   int8_t* k28 = qk8 + 3 * QK2;
    int8_t* img8 = in8;            int8_t* tab8 = in8 + QK2;
    __half* v1r = v2;              __half* v2r = v2 + QK2;
    __half* Sh1 = Sh;              __half* Sh2 = Sh + (size_t)NR * NR;

    // ---- launches 0-2: input conversions + combined weight prep ----
    const size_t tot = (size_t)NR * DC;
    convert_split<<<(unsigned)((tot / 4 + 255) / 256), 256>>>(img, img2, img8, DC, tot);
    convert_split<<<(unsigned)((tot / 4 + 255) / 256), 256>>>(tab, tab2, tab8, DC, tot);
    weight_prep<<<dim3(64, 64, 7), dim3(32, 8)>>>(
        Wqi, Wkt, Wvt, Wqt, Wki, Wvi, Wo,
        wqi2, wkt2, wvt2, wqt2, wki2, wvi2, wo2, w8);

    // ---- launch 3: all 4 Q/K projections (int8 corr + fp16 hi·hi + emit8) ----
    {
        GB4 b = {{ { img2, wqi2, img8, wqi8, bqi, nullptr, q12, q18, nullptr },
                   { tab2, wkt2, tab8, wkt8, bkt, nullptr, k12, k18, nullptr },
                   { tab2, wqt2, tab8, wqt8, bqt, nullptr, q22, q28, nullptr },
                   { img2, wki2, img8, wki8, bki, nullptr, k22, k28, nullptr } }};
        hgemm3<1,1,4,1><<<dim3(DC/128, NR/128, 4), TPB, GSMEM>>>(
            b, DC, 2*DC, 2*DC, 2*DC, 2*DC, DC, SCOMB_PROJ);
    }
    // ---- launch 4: both V projections (row-major, 1-pass) ----
    {
        GB4 b = {{ { tab2, wvt2, nullptr, nullptr, bvt, nullptr, v1r, nullptr, nullptr },
                   { img2, wvi2, nullptr, nullptr, bvi, nullptr, v2r, nullptr, nullptr },
                   {}, {} }};
        hgemm3<1,1,1,0><<<dim3(DC/128, NR/128, 2), TPB, GSMEM>>>(
            b, DC, 2*DC, 2*DC, 0, 2*DC, DC, 0.0f);
    }
    // ---- launch 5: reset rowmax keys ----
    cudaMemsetAsync(rmax, 0, 2 * NR * sizeof(unsigned));
    // ---- launch 6: screening QK (int8 hi·hi) + rowmax atomics ----
    {
        GB4 b = {{ { nullptr, nullptr, q18, k18, nullptr, nullptr, Sh1, nullptr, rmax },
                   { nullptr, nullptr, q28, k28, nullptr, nullptr, Sh2, nullptr, rmax + NR },
                   {}, {} }};
        hgemm3<2,0,8,0><<<dim3(NR/128, NR/128, 2), TPB, GSMEM>>>(
            b, DC, 0, 0, 2*DC, NR, 0, SCOMB_SCR);
    }
    // ---- launch 7: candidate selection (pure streaming) ----
    select_candidates<<<dim3(NR, 2), 256>>>(Sh, rmax, PidxP, PcntP);
    // ---- launch 8: exact logits + softmax (pure gather, L2-resident k) ----
    exact_softmax<<<dim3(NR, 2), 256>>>(q12, k12, q22, k22, PidxP, Pval, PcntP);
    // ---- launch 9: sparse P·V ----
    sparse_pv<<<dim3(NR, 2), 256>>>(PidxP, Pval, PcntP, v2, fused2);
    // ---- launch 10: output projection (1-pass, fp32 out) ----
    {
        GB4 b = {{ { fused2, wo2, nullptr, nullptr, bo, out, nullptr, nullptr, nullptr },
                   {}, {}, {} }};
        hgemm3<0,1,1,0><<<dim3(2*DC/128, NR/128, 1), TPB, GSMEM>>>(
            b, 2*DC, 4*DC, 4*DC, 0, 2*DC, 0, 0.0f);
    }
}

// round 15
// speedup vs baseline: 1.2404x; 1.2404x over previous
#include <cuda_runtime.h>
#include <cuda_fp16.h>
#include <cstdint>

#define NR 8192
#define DC 1024
#define PCAP 1024                    // sparse-P capacity per row
#define PTAU 1e-9f                   // normalized-prob threshold

// int8 scales (validated R10-R12)
#define S8_HI 32.0f
#define S8_LO 65536.0f
#define SCOMB_QK   (1.0f / 2097152.0f)     // 2^-21
#define SIN_HI 16.0f
#define SIN_LO 16384.0f
#define SW_HI  1024.0f
#define SW_LO  1048576.0f
#define SCOMB_PROJ (1.0f / 16777216.0f)    // 2^-24

// ---------------------------------------------------------------------------
// Static device scratch. Split-fp16 tensors stored [rows, 2K]: hi | lo.
// ---------------------------------------------------------------------------
__device__ float  g_S[(size_t)2 * NR * NR];             // logits (branch 0/1)
__device__ __half g_img2[(size_t)NR * 2 * DC];
__device__ __half g_tab2[(size_t)NR * 2 * DC];
__device__ int8_t g_in8[(size_t)2 * NR * 2 * DC];       // img8, tab8 (hi|lo)
__device__ __half g_w2[(size_t)6 * DC * 2 * DC];        // 6x W^T [1024,2048]
__device__ int8_t g_w8[(size_t)6 * DC * 2 * DC];        // 6x W^T int8 (hi|lo)
__device__ __half g_wo2[(size_t)2 * DC * 4 * DC];       // Wo^T [2048,4096]
__device__ __half g_qk2[(size_t)4 * NR * 2 * DC];       // q1,k1,q2,k2 fp16 hi|lo
__device__ int8_t g_qk8[(size_t)4 * NR * 2 * DC];       // q1,k1,q2,k2 int8 hi|lo
__device__ __half g_v2[(size_t)2 * NR * 2 * DC];        // v1,v2 row-major hi|lo
__device__ int    g_Pidx[(size_t)2 * NR * PCAP];        // sparse P indices
__device__ float  g_Pval[(size_t)2 * NR * PCAP];        // sparse P probs (fp32)
__device__ int    g_Pcnt[2 * NR];
__device__ __half g_fused2[(size_t)NR * 4 * DC];

// ---------------------------------------------------------------------------
// helpers
// ---------------------------------------------------------------------------
__device__ __forceinline__ uint32_t smem_u32(const void* p) {
    uint32_t a;
    asm("{ .reg .u64 t; cvta.to.shared.u64 t, %1; cvt.u32.u64 %0, t; }" : "=r"(a) : "l"(p));
    return a;
}
__device__ __forceinline__ void cp16(uint32_t d, const void* g) {
    asm volatile("cp.async.cg.shared.global [%0], [%1], 16;"
                 :: "r"(d), "l"(__cvta_generic_to_global(g)) : "memory");
}
__device__ __forceinline__ void ldm4(uint32_t* r, uint32_t a) {
    asm volatile("ldmatrix.sync.aligned.m8n8.x4.shared.b16 {%0,%1,%2,%3}, [%4];"
                 : "=r"(r[0]), "=r"(r[1]), "=r"(r[2]), "=r"(r[3]) : "r"(a));
}
__device__ __forceinline__ void mma16816(float* d, const uint32_t* a, const uint32_t* b) {
    asm("mma.sync.aligned.m16n8k16.row.col.f32.f16.f16.f32 "
        "{%0,%1,%2,%3}, {%4,%5,%6,%7}, {%8,%9}, {%0,%1,%2,%3};"
        : "+f"(d[0]), "+f"(d[1]), "+f"(d[2]), "+f"(d[3])
        : "r"(a[0]), "r"(a[1]), "r"(a[2]), "r"(a[3]), "r"(b[0]), "r"(b[1]));
}
__device__ __forceinline__ void mma16832s8(int* d, const uint32_t* a, const uint32_t* b) {
    asm("mma.sync.aligned.m16n8k32.row.col.s32.s8.s8.s32 "
        "{%0,%1,%2,%3}, {%4,%5,%6,%7}, {%8,%9}, {%0,%1,%2,%3};"
        : "+r"(d[0]), "+r"(d[1]), "+r"(d[2]), "+r"(d[3])
        : "r"(a[0]), "r"(a[1]), "r"(a[2]), "r"(a[3]), "r"(b[0]), "r"(b[1]));
}
__device__ __forceinline__ __half2 split_hi(float x0, float x1, __half2& lo) {
    __half h0 = __float2half_rn(x0), h1 = __float2half_rn(x1);
    lo = __halves2half2(__float2half_rn(x0 - __half2float(h0)),
                        __float2half_rn(x1 - __half2float(h1)));
    return __halves2half2(h0, h1);
}
__device__ __forceinline__ int8_t q8clamp(float x, float s) {
    int v = __float2int_rn(x * s);
    v = v > 127 ? 127 : (v < -127 ? -127 : v);
    return (int8_t)v;
}

// ---------------------------------------------------------------------------
// Batched split NT GEMM (validated R11/R12 core):  C = A . B^T per blockIdx.z
// PASSES=4: int8 corrections (2 sweeps, shared s32 acc) + fp16 hi·hi (fp32 acc)
// PASSES=1: hi·hi only.
// ---------------------------------------------------------------------------
#define TPB 256
#define AST 144
#define STG (128 * AST * 2)
#define GSMEM (3 * STG)

struct GB { const __half* A; const __half* B; const int8_t* A8; const int8_t* B8;
            const float* bias; float* Cf; __half* Ch; int8_t* C8; };
struct GB4 { GB g[4]; };

template <int OUT_MODE, int BIAS, int PASSES, int EMIT8>
__global__ __launch_bounds__(TPB, 2)
void hgemm3(const __grid_constant__ GB4 batch, int K,
            size_t ldA, size_t ldB, size_t ld8, int ldc, int lo_off, float s_comb)
{
    extern __shared__ char smc[];
    const uint32_t sb = smem_u32(smc);
    const GB gb = batch.g[blockIdx.z];
    const int tid = threadIdx.x;
    const int wid = tid >> 5, lane = tid & 31;
    const int g = lane >> 2, t = lane & 3;
    const int wm = wid & 1, wn = wid >> 1;
    const int m0 = blockIdx.y * 128, n0 = blockIdx.x * 128;

    const int K64 = K >> 6;
    const int corr  = (PASSES == 4) ? K64 : 0;
    const int total = corr + K64;

    const int lr = tid >> 3;
    const int lc  = (tid & 7) * 8;
    const int lcB = (tid & 7) * 16;

    auto load_stage = [&](int s, int step) {
        if (step < total) {
            const uint32_t da = sb + s * STG + lr * AST + lcB;
            const uint32_t db = da + 128 * AST;
            if (PASSES == 4 && step < corr) {
                const int spw = K >> 7;
                const int swp = step / spw, kk = step - swp * spw;
                const int a8o = swp ? K : 0;
                const int b8o = swp ? 0 : K;
                const int8_t* ga  = gb.A8 + (size_t)(m0 + lr) * ld8 + a8o + kk * 128 + lcB;
                const int8_t* gbp = gb.B8 + (size_t)(n0 + lr) * ld8 + b8o + kk * 128 + lcB;
#pragma unroll
                for (int i = 0; i < 4; ++i) {
                    cp16(da + i * 32 * AST, ga  + (size_t)i * 32 * ld8);
                    cp16(db + i * 32 * AST, gbp + (size_t)i * 32 * ld8);
                }
            } else {
                const int kk = step - corr;
                const __half* ga  = gb.A + (size_t)(m0 + lr) * ldA + (size_t)kk * 64 + lc;
                const __half* gbp = gb.B + (size_t)(n0 + lr) * ldB + (size_t)kk * 64 + lc;
#pragma unroll
                for (int i = 0; i < 4; ++i) {
                    cp16(da + i * 32 * AST, ga  + (size_t)i * 32 * ldA);
                    cp16(db + i * 32 * AST, gbp + (size_t)i * 32 * ldB);
                }
            }
        }
        asm volatile("cp.async.commit_group;" ::: "memory");
    };

    const uint32_t aoff = (uint32_t)(wm * 64 + (lane & 15)) * AST + ((lane >> 4) << 4);
    const uint32_t boff = 128 * AST +
        (uint32_t)(wn * 32 + ((lane & 7) | ((lane >> 1) & 8))) * AST +
        (((lane >> 3) & 1) << 4);

    load_stage(0, 0);
    load_stage(1, 1);

    int iacc[4][4][4];
    if (PASSES == 4) {
#pragma unroll
        for (int i = 0; i < 4; ++i)
#pragma unroll
            for (int j = 0; j < 4; ++j)
#pragma unroll
                for (int r = 0; r < 4; ++r) iacc[i][j][r] = 0;
    }

    for (int step = 0; step < corr; ++step) {
        asm volatile("cp.async.wait_group 1;" ::: "memory");
        __syncthreads();
        load_stage((step + 2) % 3, step + 2);
        const uint32_t sbase = sb + (step % 3) * STG;
#pragma unroll
        for (int kh = 0; kh < 4; ++kh) {
            const uint32_t ko = kh * 32;
            uint32_t af[4][4], bf[4][2];
#pragma unroll
            for (int mt = 0; mt < 4; ++mt)
                ldm4(af[mt], sbase + aoff + (uint32_t)mt * 16 * AST + ko);
#pragma unroll
            for (int np = 0; np < 2; ++np) {
                uint32_t r[4];
                ldm4(r, sbase + boff + (uint32_t)np * 16 * AST + ko);
                bf[np * 2][0] = r[0];      bf[np * 2][1] = r[1];
                bf[np * 2 + 1][0] = r[2];  bf[np * 2 + 1][1] = r[3];
            }
#pragma unroll
            for (int mt = 0; mt < 4; ++mt)
#pragma unroll
                for (int nt = 0; nt < 4; ++nt)
                    mma16832s8(iacc[mt][nt], af[mt], bf[nt]);
        }
    }

    float acc[4][4][4];
#pragma unroll
    for (int i = 0; i < 4; ++i)
#pragma unroll
        for (int j = 0; j < 4; ++j) {
            if (PASSES == 4) {
#pragma unroll
                for (int r = 0; r < 4; ++r)
                    acc[i][j][r] = (float)iacc[i][j][r] * s_comb;
            } else {
#pragma unroll
                for (int r = 0; r < 4; ++r) acc[i][j][r] = 0.0f;
            }
        }

    for (int step = corr; step < total; ++step) {
        asm volatile("cp.async.wait_group 1;" ::: "memory");
        __syncthreads();
        load_stage((step + 2) % 3, step + 2);
        const uint32_t sbase = sb + (step % 3) * STG;
#pragma unroll
        for (int kh = 0; kh < 4; ++kh) {
            const uint32_t ko = kh * 32;
            uint32_t af[4][4], bf[4][2];
#pragma unroll
            for (int mt = 0; mt < 4; ++mt)
                ldm4(af[mt], sbase + aoff + (uint32_t)mt * 16 * AST + ko);
#pragma unroll
            for (int np = 0; np < 2; ++np) {
                uint32_t r[4];
                ldm4(r, sbase + boff + (uint32_t)np * 16 * AST + ko);
                bf[np * 2][0] = r[0];      bf[np * 2][1] = r[1];
                bf[np * 2 + 1][0] = r[2];  bf[np * 2 + 1][1] = r[3];
            }
#pragma unroll
            for (int mt = 0; mt < 4; ++mt)
#pragma unroll
                for (int nt = 0; nt < 4; ++nt)
                    mma16816(acc[mt][nt], af[mt], bf[nt]);
        }
    }

    // ---- epilogue ----
#pragma unroll
    for (int mt = 0; mt < 4; ++mt) {
        const int r0 = m0 + wm * 64 + mt * 16 + g;
        const int r1 = r0 + 8;
#pragma unroll
        for (int nt = 0; nt < 4; ++nt) {
            const int col = n0 + wn * 32 + nt * 8 + 2 * t;
            float v00 = acc[mt][nt][0], v01 = acc[mt][nt][1];
            float v10 = acc[mt][nt][2], v11 = acc[mt][nt][3];
            if (BIAS == 1) {
                const float b0 = gb.bias[col], b1 = gb.bias[col + 1];
                v00 += b0; v01 += b1; v10 += b0; v11 += b1;
            } else if (BIAS == 2) {
                const float b0 = gb.bias[r0], b1 = gb.bias[r1];
                v00 += b0; v01 += b0; v10 += b1; v11 += b1;
            }
            if (OUT_MODE == 0) {
                *reinterpret_cast<float2*>(&gb.Cf[(size_t)r0 * ldc + col]) = make_float2(v00, v01);
                *reinterpret_cast<float2*>(&gb.Cf[(size_t)r1 * ldc + col]) = make_float2(v10, v11);
            } else {
                __half2 lo0, lo1;
                __half2 hi0 = split_hi(v00, v01, lo0);
                __half2 hi1 = split_hi(v10, v11, lo1);
                __half2* p0 = reinterpret_cast<__half2*>(&gb.Ch[(size_t)r0 * ldc + col]);
                __half2* p1 = reinterpret_cast<__half2*>(&gb.Ch[(size_t)r1 * ldc + col]);
                p0[0] = hi0;  p0[lo_off / 2] = lo0;
                p1[0] = hi1;  p1[lo_off / 2] = lo1;
                if (EMIT8) {
                    const float l00 = __low2float(lo0), l01 = __high2float(lo0);
                    const float l10 = __low2float(lo1), l11 = __high2float(lo1);
                    char2 h8a = { q8clamp(v00, S8_HI), q8clamp(v01, S8_HI) };
                    char2 h8b = { q8clamp(v10, S8_HI), q8clamp(v11, S8_HI) };
                    char2 l8a = { q8clamp(l00, S8_LO), q8clamp(l01, S8_LO) };
                    char2 l8b = { q8clamp(l10, S8_LO), q8clamp(l11, S8_LO) };
                    *reinterpret_cast<char2*>(&gb.C8[(size_t)r0 * ldc + col])          = h8a;
                    *reinterpret_cast<char2*>(&gb.C8[(size_t)r1 * ldc + col])          = h8b;
                    *reinterpret_cast<char2*>(&gb.C8[(size_t)r0 * ldc + lo_off + col]) = l8a;
                    *reinterpret_cast<char2*>(&gb.C8[(size_t)r1 * ldc + lo_off + col]) = l8b;
                }
            }
        }
    }
}

// ---------------------------------------------------------------------------
// fp32 [R,C] -> split fp16 [R,2C] + int8 [R,2C]
// ---------------------------------------------------------------------------
__global__ __launch_bounds__(256)
void convert_split(const float* __restrict__ in, __half* __restrict__ out,
                   int8_t* __restrict__ out8, int C, size_t total)
{
    size_t i = ((size_t)blockIdx.x * 256 + threadIdx.x) * 4;
    if (i >= total) return;
    float4 v = *reinterpret_cast<const float4*>(&in[i]);
    size_t r = i / C;
    int c = (int)(i - r * C);
    __half2 lo0, lo1;
    __half2 hi0 = split_hi(v.x, v.y, lo0);
    __half2 hi1 = split_hi(v.z, v.w, lo1);
    __half* row = out + r * (2 * (size_t)C);
    *reinterpret_cast<__half2*>(&row[c])         = hi0;
    *reinterpret_cast<__half2*>(&row[c + 2])     = hi1;
    *reinterpret_cast<__half2*>(&row[C + c])     = lo0;
    *reinterpret_cast<__half2*>(&row[C + c + 2]) = lo1;
    int8_t* row8 = out8 + r * (2 * (size_t)C);
    char4 h8 = { q8clamp(__low2float(hi0), SIN_HI), q8clamp(__high2float(hi0), SIN_HI),
                 q8clamp(__low2float(hi1), SIN_HI), q8clamp(__high2float(hi1), SIN_HI) };
    char4 l8 = { q8clamp(__low2float(lo0), SIN_LO), q8clamp(__high2float(lo0), SIN_LO),
                 q8clamp(__low2float(lo1), SIN_LO), q8clamp(__high2float(lo1), SIN_LO) };
    *reinterpret_cast<char4*>(&row8[c])     = h8;
    *reinterpret_cast<char4*>(&row8[C + c]) = l8;
}

// ---------------------------------------------------------------------------
// All 7 weight transposes in ONE launch (+ int8 for projection weights)
// ---------------------------------------------------------------------------
__global__ __launch_bounds__(256)
void weight_prep(const float* w0, const float* w1, const float* w2c,
                 const float* w3, const float* w4, const float* w5,
                 const float* w6,
                 __half* o0, __half* o1, __half* o2, __half* o3,
                 __half* o4, __half* o5, __half* o6, int8_t* o8base)
{
    const float* src; __half* dst; int R, C;
    switch (blockIdx.z) {
        case 0: src = w0; dst = o0; R = DC; C = DC; break;
        case 1: src = w1; dst = o1; R = DC; C = DC; break;
        case 2: src = w2c; dst = o2; R = DC; C = DC; break;
        case 3: src = w3; dst = o3; R = DC; C = DC; break;
        case 4: src = w4; dst = o4; R = DC; C = DC; break;
        case 5: src = w5; dst = o5; R = DC; C = DC; break;
        default: src = w6; dst = o6; R = 2 * DC; C = 2 * DC; break;
    }
    const int bx = blockIdx.x * 32, by = blockIdx.y * 32;
    if (bx >= C || by >= R) return;
    int8_t* dst8 = (blockIdx.z < 6)
        ? o8base + (size_t)blockIdx.z * DC * 2 * DC : nullptr;

    __shared__ float tl[32][33];
    const int tx = threadIdx.x, ty = threadIdx.y;
#pragma unroll
    for (int j = ty; j < 32; j += 8)
        tl[j][tx] = src[(size_t)(by + j) * C + bx + tx];
    __syncthreads();
#pragma unroll
    for (int j = ty; j < 32; j += 8) {
        const float v = tl[tx][j];
        const __half h = __float2half_rn(v);
        const float hf = __half2float(h);
        const __half l = __float2half_rn(v - hf);
        __half* row = dst + (size_t)(bx + j) * (2 * (size_t)R);
        row[by + tx]     = h;
        row[R + by + tx] = l;
        if (dst8) {
            int8_t* row8 = dst8 + (size_t)(bx + j) * (2 * (size_t)R);
            row8[by + tx]     = q8clamp(hf, SW_HI);
            row8[R + by + tx] = q8clamp(__half2float(l), SW_LO);
        }
    }
}

// ---------------------------------------------------------------------------
// Row softmax + deterministic in-order sparse compaction (warp-scan version).
// One block per (row, branch). Emits (idx, fp32 prob) for p > PTAU, <= PCAP.
// ---------------------------------------------------------------------------
__global__ __launch_bounds__(256)
void softmax_sparse(const float* __restrict__ S,
                    int* __restrict__ Pidx, float* __restrict__ Pval,
                    int* __restrict__ Pcnt)
{
    __shared__ float row[NR];
    __shared__ float red[256];
    __shared__ int   wtot[8];
    __shared__ int   lidx[PCAP];
    __shared__ float lp[PCAP];
    __shared__ int   ltot;
    __shared__ int   chunk_tot;

    const int br = blockIdx.y;
    const size_t soff = (size_t)br * NR * NR + (size_t)blockIdx.x * NR;
    const float* p = S + soff;
    const int tid = threadIdx.x;
    const int lane = tid & 31, wrp = tid >> 5;

    float lmax = -3.0e38f;
    for (int i = tid * 4; i < NR; i += 1024) {
        float4 v = *reinterpret_cast<const float4*>(&p[i]);
        *reinterpret_cast<float4*>(&row[i]) = v;
        lmax = fmaxf(lmax, fmaxf(fmaxf(v.x, v.y), fmaxf(v.z, v.w)));
    }
    red[tid] = lmax;
    __syncthreads();
#pragma unroll
    for (int s = 128; s > 0; s >>= 1) {
        if (tid < s) red[tid] = fmaxf(red[tid], red[tid + s]);
        __syncthreads();
    }
    const float bmax = red[0];
    __syncthreads();

    float lsum = 0.0f;
    for (int i = tid * 4; i < NR; i += 1024) {
        float4 v = *reinterpret_cast<float4*>(&row[i]);
        v.x = __expf(v.x - bmax); v.y = __expf(v.y - bmax);
        v.z = __expf(v.z - bmax); v.w = __expf(v.w - bmax);
        lsum += v.x + v.y + v.z + v.w;
        *reinterpret_cast<float4*>(&row[i]) = v;
    }
    red[tid] = lsum;
    __syncthreads();
#pragma unroll
    for (int s = 128; s > 0; s >>= 1) {
        if (tid < s) red[tid] += red[tid + s];
        __syncthreads();
    }
    const float inv = 1.0f / red[0];
    if (tid == 0) ltot = 0;
    __syncthreads();

    // ---- in-order compaction (warp-shuffle scan + cross-warp scan) ----
    for (int base = 0; base < NR; base += 1024) {
        float4 v = *reinterpret_cast<const float4*>(&row[base + tid * 4]);
        float pe[4] = { v.x * inv, v.y * inv, v.z * inv, v.w * inv };
        const int c = (pe[0] > PTAU) + (pe[1] > PTAU) + (pe[2] > PTAU) + (pe[3] > PTAU);
        int pre = c;
#pragma unroll
        for (int s = 1; s < 32; s <<= 1) {
            int n = __shfl_up_sync(0xffffffffu, pre, s);
            if (lane >= s) pre += n;
        }
        if (lane == 31) wtot[wrp] = pre;
        __syncthreads();
        if (tid == 0) {
            int r = 0;
#pragma unroll
            for (int w = 0; w < 8; ++w) { const int t2 = wtot[w]; wtot[w] = r; r += t2; }
            chunk_tot = r;
        }
        __syncthreads();
        int o = ltot + wtot[wrp] + pre - c;
#pragma unroll
        for (int e = 0; e < 4; ++e) {
            if (pe[e] > PTAU) {
                if (o < PCAP) { lidx[o] = base + tid * 4 + e; lp[o] = pe[e]; }
                ++o;
            }
        }
        __syncthreads();
        if (tid == 0) ltot += chunk_tot;
        __syncthreads();
    }

    const int cnt = ltot < PCAP ? ltot : PCAP;
    const size_t loff = ((size_t)br * NR + blockIdx.x) * PCAP;
    for (int i = tid; i < cnt; i += 256) {
        Pidx[loff + i] = lidx[i];
        Pval[loff + i] = lp[i];
    }
    if (tid == 0) Pcnt[br * NR + blockIdx.x] = cnt;
}

// ---------------------------------------------------------------------------
// Sparse P·V: one block per (row, branch). 8-byte V loads.
// ---------------------------------------------------------------------------
__global__ __launch_bounds__(256)
void sparse_pv(const int* __restrict__ Pidx, const float* __restrict__ Pval,
               const int* __restrict__ Pcnt, const __half* __restrict__ v2,
               __half* __restrict__ fused2)
{
    __shared__ int   sidx[128];
    __shared__ float sval[128];
    const int rowi = blockIdx.x, br = blockIdx.y;
    const size_t loff = ((size_t)br * NR + rowi) * PCAP;
    const int cnt = Pcnt[br * NR + rowi];
    const __half* V = v2 + (size_t)br * NR * 2 * DC;
    const int tid = threadIdx.x;
    const int d = tid * 4;

    float a0 = 0.f, a1 = 0.f, a2 = 0.f, a3 = 0.f;
    for (int base = 0; base < cnt; base += 128) {
        const int n = min(128, cnt - base);
        if (tid < n) { sidx[tid] = Pidx[loff + base + tid]; sval[tid] = Pval[loff + base + tid]; }
        __syncthreads();
#pragma unroll 4
        for (int j = 0; j < n; ++j) {
            const float pj = sval[j];
            const float2 hv = *reinterpret_cast<const float2*>(
                V + (size_t)sidx[j] * (2 * DC) + d);
            const __half2* hh = reinterpret_cast<const __half2*>(&hv);
            a0 = fmaf(pj, __low2float(hh[0]), a0);
            a1 = fmaf(pj, __high2float(hh[0]), a1);
            a2 = fmaf(pj, __low2float(hh[1]), a2);
            a3 = fmaf(pj, __high2float(hh[1]), a3);
        }
        __syncthreads();
    }

    const int col = (br == 0 ? DC : 0) + d;
    __half2 lo0, lo1;
    __half2 hi0 = split_hi(a0, a1, lo0);
    __half2 hi1 = split_hi(a2, a3, lo1);
    __half* frow = fused2 + (size_t)rowi * 4 * DC;
    *reinterpret_cast<__half2*>(&frow[col])              = hi0;
    *reinterpret_cast<__half2*>(&frow[col + 2])          = hi1;
    *reinterpret_cast<__half2*>(&frow[2 * DC + col])     = lo0;
    *reinterpret_cast<__half2*>(&frow[2 * DC + col + 2]) = lo1;
}

// ---------------------------------------------------------------------------
// Launch sequence (identical to R12)
// ---------------------------------------------------------------------------
extern "C" void kernel_launch(void* const* d_in, const int* in_sizes, int n_in,
                              void* d_out, int out_size)
{
    const float* img = (const float*)d_in[0];
    const float* tab = (const float*)d_in[1];
    const float* Wqi = (const float*)d_in[2];  const float* bqi = (const float*)d_in[3];
    const float* Wkt = (const float*)d_in[4];  const float* bkt = (const float*)d_in[5];
    const float* Wvt = (const float*)d_in[6];  const float* bvt = (const float*)d_in[7];
    const float* Wqt = (const float*)d_in[8];  const float* bqt = (const float*)d_in[9];
    const float* Wki = (const float*)d_in[10]; const float* bki = (const float*)d_in[11];
    const float* Wvi = (const float*)d_in[12]; const float* bvi = (const float*)d_in[13];
    const float* Wo  = (const float*)d_in[14]; const float* bo  = (const float*)d_in[15];
    float* out = (float*)d_out;

    cudaFuncSetAttribute(hgemm3<0,0,4,0>, cudaFuncAttributeMaxDynamicSharedMemorySize, GSMEM);
    cudaFuncSetAttribute(hgemm3<0,1,1,0>, cudaFuncAttributeMaxDynamicSharedMemorySize, GSMEM);
    cudaFuncSetAttribute(hgemm3<1,1,1,0>, cudaFuncAttributeMaxDynamicSharedMemorySize, GSMEM);
    cudaFuncSetAttribute(hgemm3<1,1,4,1>, cudaFuncAttributeMaxDynamicSharedMemorySize, GSMEM);

    float *S, *Pval;
    __half *img2, *tab2, *w2, *wo2, *qk2, *v2, *fused2;
    int8_t *qk8, *in8, *w8;
    int *PidxP, *PcntP;
    cudaGetSymbolAddress((void**)&S,      g_S);
    cudaGetSymbolAddress((void**)&img2,   g_img2);
    cudaGetSymbolAddress((void**)&tab2,   g_tab2);
    cudaGetSymbolAddress((void**)&in8,    g_in8);
    cudaGetSymbolAddress((void**)&w2,     g_w2);
    cudaGetSymbolAddress((void**)&w8,     g_w8);
    cudaGetSymbolAddress((void**)&wo2,    g_wo2);
    cudaGetSymbolAddress((void**)&qk2,    g_qk2);
    cudaGetSymbolAddress((void**)&qk8,    g_qk8);
    cudaGetSymbolAddress((void**)&v2,     g_v2);
    cudaGetSymbolAddress((void**)&PidxP,  g_Pidx);
    cudaGetSymbolAddress((void**)&Pval,   g_Pval);
    cudaGetSymbolAddress((void**)&PcntP,  g_Pcnt);
    cudaGetSymbolAddress((void**)&fused2, g_fused2);

    const size_t W2SZ = (size_t)DC * 2 * DC;
    __half* wqi2 = w2 + 0 * W2SZ;  __half* wkt2 = w2 + 1 * W2SZ;
    __half* wvt2 = w2 + 2 * W2SZ;  __half* wqt2 = w2 + 3 * W2SZ;
    __half* wki2 = w2 + 4 * W2SZ;  __half* wvi2 = w2 + 5 * W2SZ;
    int8_t* wqi8 = w8 + 0 * W2SZ;  int8_t* wkt8 = w8 + 1 * W2SZ;
    int8_t* wqt8 = w8 + 3 * W2SZ;  int8_t* wki8 = w8 + 4 * W2SZ;
    const size_t QK2 = (size_t)NR * 2 * DC;
    __half* q12 = qk2 + 0 * QK2;   __half* k12 = qk2 + 1 * QK2;
    __half* q22 = qk2 + 2 * QK2;   __half* k22 = qk2 + 3 * QK2;
    int8_t* q18 = qk8 + 0 * QK2;   int8_t* k18 = qk8 + 1 * QK2;
    int8_t* q28 = qk8 + 2 * QK2;   int8_t* k28 = qk8 + 3 * QK2;
    int8_t* img8 = in8;            int8_t* tab8 = in8 + QK2;
    __half* v1r = v2;              __half* v2r = v2 + QK2;
    float*  S_1 = S;               float*  S_2 = S + (size_t)NR * NR;

    // ---- launches 0-2: input conversions + combined weight prep ----
    const size_t tot = (size_t)NR * DC;
    convert_split<<<(unsigned)((tot / 4 + 255) / 256), 256>>>(img, img2, img8, DC, tot);
    convert_split<<<(unsigned)((tot / 4 + 255) / 256), 256>>>(tab, tab2, tab8, DC, tot);
    weight_prep<<<dim3(64, 64, 7), dim3(32, 8)>>>(
        Wqi, Wkt, Wvt, Wqt, Wki, Wvi, Wo,
        wqi2, wkt2, wvt2, wqt2, wki2, wvi2, wo2, w8);

    // ---- launch 3: all 4 Q/K projections (int8 corr + fp16 hi·hi + emit8) ----
    {
        GB4 b = {{ { img2, wqi2, img8, wqi8, bqi, nullptr, q12, q18 },
                   { tab2, wkt2, tab8, wkt8, bkt, nullptr, k12, k18 },
                   { tab2, wqt2, tab8, wqt8, bqt, nullptr, q22, q28 },
                   { img2, wki2, img8, wki8, bki, nullptr, k22, k28 } }};
        hgemm3<1,1,4,1><<<dim3(DC/128, NR/128, 4), TPB, GSMEM>>>(
            b, DC, 2*DC, 2*DC, 2*DC, 2*DC, DC, SCOMB_PROJ);
    }
    // ---- launch 4: both V projections (row-major, 1-pass, per-col bias) ----
    {
        GB4 b = {{ { tab2, wvt2, nullptr, nullptr, bvt, nullptr, v1r, nullptr },
                   { img2, wvi2, nullptr, nullptr, bvi, nullptr, v2r, nullptr },
                   {}, {} }};
        hgemm3<1,1,1,0><<<dim3(DC/128, NR/128, 2), TPB, GSMEM>>>(
            b, DC, 2*DC, 2*DC, 0, 2*DC, DC, 0.0f);
    }
    // ---- launch 5: both QK^T (int8 corrections + fp16 hi·hi) ----
    {
        GB4 b = {{ { q12, k12, q18, k18, nullptr, S_1, nullptr, nullptr },
                   { q22, k22, q28, k28, nullptr, S_2, nullptr, nullptr },
                   {}, {} }};
        hgemm3<0,0,4,0><<<dim3(NR/128, NR/128, 2), TPB, GSMEM>>>(
            b, DC, 2*DC, 2*DC, 2*DC, NR, 0, SCOMB_QK);
    }
    // ---- launch 6: softmax + sparse compaction (both branches) ----
    softmax_sparse<<<dim3(NR, 2), 256>>>(S, PidxP, Pval, PcntP);
    // ---- launch 7: sparse P·V (both branches) ----
    sparse_pv<<<dim3(NR, 2), 256>>>(PidxP, Pval, PcntP, v2, fused2);
    // ---- launch 8: output projection (1-pass, fp32 out) ----
    {
        GB4 b = {{ { fused2, wo2, nullptr, nullptr, bo, out, nullptr, nullptr },
                   {}, {}, {} }};
        hgemm3<0,1,1,0><<<dim3(2*DC/128, NR/128, 1), TPB, GSMEM>>>(
            b, 2*DC, 4*DC, 4*DC, 0, 2*DC, 0, 0.0f);
    }
}

// round 16
// speedup vs baseline: 1.2713x; 1.0249x over previous
#include <cuda_runtime.h>
#include <cuda_fp16.h>
#include <cstdint>

#define NR 8192
#define DC 1024
#define PCAP 1024                    // sparse candidate capacity per row
#define SMARGIN 21.0f                // logit threshold below exact row max

// int8 scales (validated R10-R15)
#define S8_HI 32.0f
#define S8_LO 65536.0f
#define SCOMB_QK   (1.0f / 2097152.0f)     // 2^-21
#define SIN_HI 16.0f
#define SIN_LO 16384.0f
#define SW_HI  1024.0f
#define SW_LO  1048576.0f
#define SCOMB_PROJ (1.0f / 16777216.0f)    // 2^-24

// ---------------------------------------------------------------------------
// Static device scratch. Split-fp16 tensors stored [rows, 2K]: hi | lo.
// ---------------------------------------------------------------------------
__device__ float    g_S[(size_t)2 * NR * NR];           // logits (branch 0/1)
__device__ __half   g_img2[(size_t)NR * 2 * DC];
__device__ __half   g_tab2[(size_t)NR * 2 * DC];
__device__ int8_t   g_in8[(size_t)2 * NR * 2 * DC];     // img8, tab8 (hi|lo)
__device__ __half   g_w2[(size_t)6 * DC * 2 * DC];      // 6x W^T [1024,2048]
__device__ int8_t   g_w8[(size_t)6 * DC * 2 * DC];      // 6x W^T int8 (hi|lo)
__device__ __half   g_wo2[(size_t)2 * DC * 4 * DC];     // Wo^T [2048,4096]
__device__ __half   g_qk2[(size_t)4 * NR * 2 * DC];     // q1,k1,q2,k2 fp16 hi|lo
__device__ int8_t   g_qk8[(size_t)4 * NR * 2 * DC];     // q1,k1,q2,k2 int8 hi|lo
__device__ __half   g_v2[(size_t)2 * NR * 2 * DC];      // v1,v2 row-major hi|lo
__device__ unsigned g_rmax[2 * NR];                     // ordered-uint row maxes
__device__ __half   g_fused2[(size_t)NR * 4 * DC];

// ---------------------------------------------------------------------------
// helpers
// ---------------------------------------------------------------------------
__device__ __forceinline__ uint32_t smem_u32(const void* p) {
    uint32_t a;
    asm("{ .reg .u64 t; cvta.to.shared.u64 t, %1; cvt.u32.u64 %0, t; }" : "=r"(a) : "l"(p));
    return a;
}
__device__ __forceinline__ void cp16(uint32_t d, const void* g) {
    asm volatile("cp.async.cg.shared.global [%0], [%1], 16;"
                 :: "r"(d), "l"(__cvta_generic_to_global(g)) : "memory");
}
__device__ __forceinline__ void ldm4(uint32_t* r, uint32_t a) {
    asm volatile("ldmatrix.sync.aligned.m8n8.x4.shared.b16 {%0,%1,%2,%3}, [%4];"
                 : "=r"(r[0]), "=r"(r[1]), "=r"(r[2]), "=r"(r[3]) : "r"(a));
}
__device__ __forceinline__ void mma16816(float* d, const uint32_t* a, const uint32_t* b) {
    asm("mma.sync.aligned.m16n8k16.row.col.f32.f16.f16.f32 "
        "{%0,%1,%2,%3}, {%4,%5,%6,%7}, {%8,%9}, {%0,%1,%2,%3};"
        : "+f"(d[0]), "+f"(d[1]), "+f"(d[2]), "+f"(d[3])
        : "r"(a[0]), "r"(a[1]), "r"(a[2]), "r"(a[3]), "r"(b[0]), "r"(b[1]));
}
__device__ __forceinline__ void mma16832s8(int* d, const uint32_t* a, const uint32_t* b) {
    asm("mma.sync.aligned.m16n8k32.row.col.s32.s8.s8.s32 "
        "{%0,%1,%2,%3}, {%4,%5,%6,%7}, {%8,%9}, {%0,%1,%2,%3};"
        : "+r"(d[0]), "+r"(d[1]), "+r"(d[2]), "+r"(d[3])
        : "r"(a[0]), "r"(a[1]), "r"(a[2]), "r"(a[3]), "r"(b[0]), "r"(b[1]));
}
__device__ __forceinline__ __half2 split_hi(float x0, float x1, __half2& lo) {
    __half h0 = __float2half_rn(x0), h1 = __float2half_rn(x1);
    lo = __halves2half2(__float2half_rn(x0 - __half2float(h0)),
                        __float2half_rn(x1 - __half2float(h1)));
    return __halves2half2(h0, h1);
}
__device__ __forceinline__ int8_t q8clamp(float x, float s) {
    int v = __float2int_rn(x * s);
    v = v > 127 ? 127 : (v < -127 ? -127 : v);
    return (int8_t)v;
}
// ordered-uint encoding for float atomicMax (monotone; key(x) > 0 for all finite x)
__device__ __forceinline__ unsigned fkey(float x) {
    unsigned b = __float_as_uint(x);
    return (b & 0x80000000u) ? ~b : (b | 0x80000000u);
}
__device__ __forceinline__ float fdec(unsigned u) {
    return (u & 0x80000000u) ? __uint_as_float(u ^ 0x80000000u) : __uint_as_float(~u);
}

// ---------------------------------------------------------------------------
// Batched split NT GEMM (validated core):  C = A . B^T per blockIdx.z
// PASSES=4: int8 corrections (2 sweeps, shared s32 acc) + fp16 hi·hi (fp32 acc)
// PASSES=1: hi·hi only.  RMAX=1: epilogue also atomicMax's per-row maxes.
// ---------------------------------------------------------------------------
#define TPB 256
#define AST 144
#define STG (128 * AST * 2)
#define GSMEM (3 * STG)

struct GB { const __half* A; const __half* B; const int8_t* A8; const int8_t* B8;
            const float* bias; float* Cf; __half* Ch; int8_t* C8; unsigned* rmax; };
struct GB4 { GB g[4]; };

template <int OUT_MODE, int BIAS, int PASSES, int EMIT8, int RMAX>
__global__ __launch_bounds__(TPB, 2)
void hgemm3(const __grid_constant__ GB4 batch, int K,
            size_t ldA, size_t ldB, size_t ld8, int ldc, int lo_off, float s_comb)
{
    extern __shared__ char smc[];
    const uint32_t sb = smem_u32(smc);
    const GB gb = batch.g[blockIdx.z];
    const int tid = threadIdx.x;
    const int wid = tid >> 5, lane = tid & 31;
    const int g = lane >> 2, t = lane & 3;
    const int wm = wid & 1, wn = wid >> 1;
    const int m0 = blockIdx.y * 128, n0 = blockIdx.x * 128;

    const int K64 = K >> 6;
    const int corr  = (PASSES == 4) ? K64 : 0;
    const int total = corr + K64;

    const int lr = tid >> 3;
    const int lc  = (tid & 7) * 8;
    const int lcB = (tid & 7) * 16;

    auto load_stage = [&](int s, int step) {
        if (step < total) {
            const uint32_t da = sb + s * STG + lr * AST + lcB;
            const uint32_t db = da + 128 * AST;
            if (PASSES == 4 && step < corr) {
                const int spw = K >> 7;
                const int swp = step / spw, kk = step - swp * spw;
                const int a8o = swp ? K : 0;
                const int b8o = swp ? 0 : K;
                const int8_t* ga  = gb.A8 + (size_t)(m0 + lr) * ld8 + a8o + kk * 128 + lcB;
                const int8_t* gbp = gb.B8 + (size_t)(n0 + lr) * ld8 + b8o + kk * 128 + lcB;
#pragma unroll
                for (int i = 0; i < 4; ++i) {
                    cp16(da + i * 32 * AST, ga  + (size_t)i * 32 * ld8);
                    cp16(db + i * 32 * AST, gbp + (size_t)i * 32 * ld8);
                }
            } else {
                const int kk = step - corr;
                const __half* ga  = gb.A + (size_t)(m0 + lr) * ldA + (size_t)kk * 64 + lc;
                const __half* gbp = gb.B + (size_t)(n0 + lr) * ldB + (size_t)kk * 64 + lc;
#pragma unroll
                for (int i = 0; i < 4; ++i) {
                    cp16(da + i * 32 * AST, ga  + (size_t)i * 32 * ldA);
                    cp16(db + i * 32 * AST, gbp + (size_t)i * 32 * ldB);
                }
            }
        }
        asm volatile("cp.async.commit_group;" ::: "memory");
    };

    const uint32_t aoff = (uint32_t)(wm * 64 + (lane & 15)) * AST + ((lane >> 4) << 4);
    const uint32_t boff = 128 * AST +
        (uint32_t)(wn * 32 + ((lane & 7) | ((lane >> 1) & 8))) * AST +
        (((lane >> 3) & 1) << 4);

    load_stage(0, 0);
    load_stage(1, 1);

    int iacc[4][4][4];
    if (PASSES == 4) {
#pragma unroll
        for (int i = 0; i < 4; ++i)
#pragma unroll
            for (int j = 0; j < 4; ++j)
#pragma unroll
                for (int r = 0; r < 4; ++r) iacc[i][j][r] = 0;
    }

    for (int step = 0; step < corr; ++step) {
        asm volatile("cp.async.wait_group 1;" ::: "memory");
        __syncthreads();
        load_stage((step + 2) % 3, step + 2);
        const uint32_t sbase = sb + (step % 3) * STG;
#pragma unroll
        for (int kh = 0; kh < 4; ++kh) {
            const uint32_t ko = kh * 32;
            uint32_t af[4][4], bf[4][2];
#pragma unroll
            for (int mt = 0; mt < 4; ++mt)
                ldm4(af[mt], sbase + aoff + (uint32_t)mt * 16 * AST + ko);
#pragma unroll
            for (int np = 0; np < 2; ++np) {
                uint32_t r[4];
                ldm4(r, sbase + boff + (uint32_t)np * 16 * AST + ko);
                bf[np * 2][0] = r[0];      bf[np * 2][1] = r[1];
                bf[np * 2 + 1][0] = r[2];  bf[np * 2 + 1][1] = r[3];
            }
#pragma unroll
            for (int mt = 0; mt < 4; ++mt)
#pragma unroll
                for (int nt = 0; nt < 4; ++nt)
                    mma16832s8(iacc[mt][nt], af[mt], bf[nt]);
        }
    }

    float acc[4][4][4];
#pragma unroll
    for (int i = 0; i < 4; ++i)
#pragma unroll
        for (int j = 0; j < 4; ++j) {
            if (PASSES == 4) {
#pragma unroll
                for (int r = 0; r < 4; ++r)
                    acc[i][j][r] = (float)iacc[i][j][r] * s_comb;
            } else {
#pragma unroll
                for (int r = 0; r < 4; ++r) acc[i][j][r] = 0.0f;
            }
        }

    for (int step = corr; step < total; ++step) {
        asm volatile("cp.async.wait_group 1;" ::: "memory");
        __syncthreads();
        load_stage((step + 2) % 3, step + 2);
        const uint32_t sbase = sb + (step % 3) * STG;
#pragma unroll
        for (int kh = 0; kh < 4; ++kh) {
            const uint32_t ko = kh * 32;
            uint32_t af[4][4], bf[4][2];
#pragma unroll
            for (int mt = 0; mt < 4; ++mt)
                ldm4(af[mt], sbase + aoff + (uint32_t)mt * 16 * AST + ko);
#pragma unroll
            for (int np = 0; np < 2; ++np) {
                uint32_t r[4];
                ldm4(r, sbase + boff + (uint32_t)np * 16 * AST + ko);
                bf[np * 2][0] = r[0];      bf[np * 2][1] = r[1];
                bf[np * 2 + 1][0] = r[2];  bf[np * 2 + 1][1] = r[3];
            }
#pragma unroll
            for (int mt = 0; mt < 4; ++mt)
#pragma unroll
                for (int nt = 0; nt < 4; ++nt)
                    mma16816(acc[mt][nt], af[mt], bf[nt]);
        }
    }

    // ---- rowmax smem init (RMAX mode; stage smem no longer read) ----
    unsigned* rm = reinterpret_cast<unsigned*>(smc);
    if (RMAX) {
        __syncthreads();
        if (tid < 128) rm[tid] = 0u;
        __syncthreads();
    }

    // ---- epilogue ----
#pragma unroll
    for (int mt = 0; mt < 4; ++mt) {
        const int r0 = m0 + wm * 64 + mt * 16 + g;
        const int r1 = r0 + 8;
#pragma unroll
        for (int nt = 0; nt < 4; ++nt) {
            const int col = n0 + wn * 32 + nt * 8 + 2 * t;
            float v00 = acc[mt][nt][0], v01 = acc[mt][nt][1];
            float v10 = acc[mt][nt][2], v11 = acc[mt][nt][3];
            if (BIAS == 1) {
                const float b0 = gb.bias[col], b1 = gb.bias[col + 1];
                v00 += b0; v01 += b1; v10 += b0; v11 += b1;
            } else if (BIAS == 2) {
                const float b0 = gb.bias[r0], b1 = gb.bias[r1];
                v00 += b0; v01 += b0; v10 += b1; v11 += b1;
            }
            if (OUT_MODE == 0) {
                *reinterpret_cast<float2*>(&gb.Cf[(size_t)r0 * ldc + col]) = make_float2(v00, v01);
                *reinterpret_cast<float2*>(&gb.Cf[(size_t)r1 * ldc + col]) = make_float2(v10, v11);
                if (RMAX) {
                    atomicMax(&rm[wm * 64 + mt * 16 + g],     fkey(fmaxf(v00, v01)));
                    atomicMax(&rm[wm * 64 + mt * 16 + g + 8], fkey(fmaxf(v10, v11)));
                }
            } else {
                __half2 lo0, lo1;
                __half2 hi0 = split_hi(v00, v01, lo0);
                __half2 hi1 = split_hi(v10, v11, lo1);
                __half2* p0 = reinterpret_cast<__half2*>(&gb.Ch[(size_t)r0 * ldc + col]);
                __half2* p1 = reinterpret_cast<__half2*>(&gb.Ch[(size_t)r1 * ldc + col]);
                p0[0] = hi0;  p0[lo_off / 2] = lo0;
                p1[0] = hi1;  p1[lo_off / 2] = lo1;
                if (EMIT8) {
                    const float l00 = __low2float(lo0), l01 = __high2float(lo0);
                    const float l10 = __low2float(lo1), l11 = __high2float(lo1);
                    char2 h8a = { q8clamp(v00, S8_HI), q8clamp(v01, S8_HI) };
                    char2 h8b = { q8clamp(v10, S8_HI), q8clamp(v11, S8_HI) };
                    char2 l8a = { q8clamp(l00, S8_LO), q8clamp(l01, S8_LO) };
                    char2 l8b = { q8clamp(l10, S8_LO), q8clamp(l11, S8_LO) };
                    *reinterpret_cast<char2*>(&gb.C8[(size_t)r0 * ldc + col])          = h8a;
                    *reinterpret_cast<char2*>(&gb.C8[(size_t)r1 * ldc + col])          = h8b;
                    *reinterpret_cast<char2*>(&gb.C8[(size_t)r0 * ldc + lo_off + col]) = l8a;
                    *reinterpret_cast<char2*>(&gb.C8[(size_t)r1 * ldc + lo_off + col]) = l8b;
                }
            }
        }
    }

    if (RMAX) {
        __syncthreads();
        if (tid < 128) atomicMax(&gb.rmax[m0 + tid], rm[tid]);
    }
}

// ---------------------------------------------------------------------------
// fp32 [R,C] -> split fp16 [R,2C] + int8 [R,2C]
// ---------------------------------------------------------------------------
__global__ __launch_bounds__(256)
void convert_split(const float* __restrict__ in, __half* __restrict__ out,
                   int8_t* __restrict__ out8, int C, size_t total)
{
    size_t i = ((size_t)blockIdx.x * 256 + threadIdx.x) * 4;
    if (i >= total) return;
    float4 v = *reinterpret_cast<const float4*>(&in[i]);
    size_t r = i / C;
    int c = (int)(i - r * C);
    __half2 lo0, lo1;
    __half2 hi0 = split_hi(v.x, v.y, lo0);
    __half2 hi1 = split_hi(v.z, v.w, lo1);
    __half* row = out + r * (2 * (size_t)C);
    *reinterpret_cast<__half2*>(&row[c])         = hi0;
    *reinterpret_cast<__half2*>(&row[c + 2])     = hi1;
    *reinterpret_cast<__half2*>(&row[C + c])     = lo0;
    *reinterpret_cast<__half2*>(&row[C + c + 2]) = lo1;
    int8_t* row8 = out8 + r * (2 * (size_t)C);
    char4 h8 = { q8clamp(__low2float(hi0), SIN_HI), q8clamp(__high2float(hi0), SIN_HI),
                 q8clamp(__low2float(hi1), SIN_HI), q8clamp(__high2float(hi1), SIN_HI) };
    char4 l8 = { q8clamp(__low2float(lo0), SIN_LO), q8clamp(__high2float(lo0), SIN_LO),
                 q8clamp(__low2float(lo1), SIN_LO), q8clamp(__high2float(lo1), SIN_LO) };
    *reinterpret_cast<char4*>(&row8[c])     = h8;
    *reinterpret_cast<char4*>(&row8[C + c]) = l8;
}

// ---------------------------------------------------------------------------
// All 7 weight transposes in ONE launch (+ int8 for projection weights)
// ---------------------------------------------------------------------------
__global__ __launch_bounds__(256)
void weight_prep(const float* w0, const float* w1, const float* w2c,
                 const float* w3, const float* w4, const float* w5,
                 const float* w6,
                 __half* o0, __half* o1, __half* o2, __half* o3,
                 __half* o4, __half* o5, __half* o6, int8_t* o8base)
{
    const float* src; __half* dst; int R, C;
    switch (blockIdx.z) {
        case 0: src = w0; dst = o0; R = DC; C = DC; break;
        case 1: src = w1; dst = o1; R = DC; C = DC; break;
        case 2: src = w2c; dst = o2; R = DC; C = DC; break;
        case 3: src = w3; dst = o3; R = DC; C = DC; break;
        case 4: src = w4; dst = o4; R = DC; C = DC; break;
        case 5: src = w5; dst = o5; R = DC; C = DC; break;
        default: src = w6; dst = o6; R = 2 * DC; C = 2 * DC; break;
    }
    const int bx = blockIdx.x * 32, by = blockIdx.y * 32;
    if (bx >= C || by >= R) return;
    int8_t* dst8 = (blockIdx.z < 6)
        ? o8base + (size_t)blockIdx.z * DC * 2 * DC : nullptr;

    __shared__ float tl[32][33];
    const int tx = threadIdx.x, ty = threadIdx.y;
#pragma unroll
    for (int j = ty; j < 32; j += 8)
        tl[j][tx] = src[(size_t)(by + j) * C + bx + tx];
    __syncthreads();
#pragma unroll
    for (int j = ty; j < 32; j += 8) {
        const float v = tl[tx][j];
        const __half h = __float2half_rn(v);
        const float hf = __half2float(h);
        const __half l = __float2half_rn(v - hf);
        __half* row = dst + (size_t)(bx + j) * (2 * (size_t)R);
        row[by + tx]     = h;
        row[R + by + tx] = l;
        if (dst8) {
            int8_t* row8 = dst8 + (size_t)(bx + j) * (2 * (size_t)R);
            row8[by + tx]     = q8clamp(hf, SW_HI);
            row8[R + by + tx] = q8clamp(__half2float(l), SW_LO);
        }
    }
}

// ---------------------------------------------------------------------------
// Fused sparse softmax + P·V. One block per (row, branch).
// Exact row max precomputed by the QK epilogue -> zero reduction pre-passes.
// Stream S row, compact candidates (logit > max-21), exp/sum, gather V.
// Deterministic: in-order compaction, fixed reduction & gather order.
// ---------------------------------------------------------------------------
__global__ __launch_bounds__(256)
void sparse_softmax_pv(const float* __restrict__ S,
                       const unsigned* __restrict__ rmax,
                       const __half* __restrict__ v2,
                       __half* __restrict__ fused2)
{
    __shared__ int   lidx[PCAP];
    __shared__ float lp[PCAP];
    __shared__ float red[256];
    __shared__ int   wtot[8];
    __shared__ int   ltot;
    __shared__ int   chunk_tot;
    __shared__ float s_inv;

    const int rowi = blockIdx.x, br = blockIdx.y;
    const int tid = threadIdx.x;
    const int lane = tid & 31, wrp = tid >> 5;
    const float* p = S + (size_t)br * NR * NR + (size_t)rowi * NR;
    const float bmax = fdec(rmax[br * NR + rowi]);
    const float thr = bmax - SMARGIN;
    if (tid == 0) ltot = 0;
    __syncthreads();

    // ---- single streaming pass: threshold + in-order compaction ----
    for (int base = 0; base < NR; base += 1024) {
        float4 v = *reinterpret_cast<const float4*>(&p[base + tid * 4]);
        float pe[4] = { v.x, v.y, v.z, v.w };
        const int c = (pe[0] > thr) + (pe[1] > thr) + (pe[2] > thr) + (pe[3] > thr);
        int pre = c;
#pragma unroll
        for (int s = 1; s < 32; s <<= 1) {
            int n = __shfl_up_sync(0xffffffffu, pre, s);
            if (lane >= s) pre += n;
        }
        if (lane == 31) wtot[wrp] = pre;
        __syncthreads();
        if (tid == 0) {
            int r = 0;
#pragma unroll
            for (int w = 0; w < 8; ++w) { const int t2 = wtot[w]; wtot[w] = r; r += t2; }
            chunk_tot = r;
        }
        __syncthreads();
        int o = ltot + wtot[wrp] + pre - c;
#pragma unroll
        for (int e = 0; e < 4; ++e) {
            if (pe[e] > thr) {
                if (o < PCAP) { lidx[o] = base + tid * 4 + e; lp[o] = pe[e]; }
                ++o;
            }
        }
        __syncthreads();
        if (tid == 0) ltot += chunk_tot;
        __syncthreads();
    }
    const int cnt = ltot < PCAP ? ltot : PCAP;

    // ---- exp + sum over candidates (max is exact -> subtract bmax) ----
    float lsum = 0.0f;
    for (int i = tid; i < cnt; i += 256) {
        const float e = __expf(lp[i] - bmax);
        lp[i] = e;
        lsum += e;
    }
    red[tid] = lsum;
    __syncthreads();
#pragma unroll
    for (int s = 128; s > 0; s >>= 1) {
        if (tid < s) red[tid] += red[tid + s];
        __syncthreads();
    }
    if (tid == 0) s_inv = 1.0f / red[0];
    __syncthreads();
    const float inv = s_inv;
    for (int i = tid; i < cnt; i += 256) lp[i] *= inv;
    __syncthreads();

    // ---- P·V gather (list resident in smem) ----
    const __half* V = v2 + (size_t)br * NR * 2 * DC;
    const int d = tid * 4;
    float a0 = 0.f, a1 = 0.f, a2 = 0.f, a3 = 0.f;
#pragma unroll 4
    for (int j = 0; j < cnt; ++j) {
        const float pj = lp[j];
        const float2 hv = *reinterpret_cast<const float2*>(
            V + (size_t)lidx[j] * (2 * DC) + d);
        const __half2* hh = reinterpret_cast<const __half2*>(&hv);
        a0 = fmaf(pj, __low2float(hh[0]), a0);
        a1 = fmaf(pj, __high2float(hh[0]), a1);
        a2 = fmaf(pj, __low2float(hh[1]), a2);
        a3 = fmaf(pj, __high2float(hh[1]), a3);
    }

    const int col = (br == 0 ? DC : 0) + d;
    __half2 lo0, lo1;
    __half2 hi0 = split_hi(a0, a1, lo0);
    __half2 hi1 = split_hi(a2, a3, lo1);
    __half* frow = fused2 + (size_t)rowi * 4 * DC;
    *reinterpret_cast<__half2*>(&frow[col])              = hi0;
    *reinterpret_cast<__half2*>(&frow[col + 2])          = hi1;
    *reinterpret_cast<__half2*>(&frow[2 * DC + col])     = lo0;
    *reinterpret_cast<__half2*>(&frow[2 * DC + col + 2]) = lo1;
}

// ---------------------------------------------------------------------------
// Launch sequence
// ---------------------------------------------------------------------------
extern "C" void kernel_launch(void* const* d_in, const int* in_sizes, int n_in,
                              void* d_out, int out_size)
{
    const float* img = (const float*)d_in[0];
    const float* tab = (const float*)d_in[1];
    const float* Wqi = (const float*)d_in[2];  const float* bqi = (const float*)d_in[3];
    const float* Wkt = (const float*)d_in[4];  const float* bkt = (const float*)d_in[5];
    const float* Wvt = (const float*)d_in[6];  const float* bvt = (const float*)d_in[7];
    const float* Wqt = (const float*)d_in[8];  const float* bqt = (const float*)d_in[9];
    const float* Wki = (const float*)d_in[10]; const float* bki = (const float*)d_in[11];
    const float* Wvi = (const float*)d_in[12]; const float* bvi = (const float*)d_in[13];
    const float* Wo  = (const float*)d_in[14]; const float* bo  = (const float*)d_in[15];
    float* out = (float*)d_out;

    cudaFuncSetAttribute(hgemm3<0,0,4,0,1>, cudaFuncAttributeMaxDynamicSharedMemorySize, GSMEM);
    cudaFuncSetAttribute(hgemm3<0,1,1,0,0>, cudaFuncAttributeMaxDynamicSharedMemorySize, GSMEM);
    cudaFuncSetAttribute(hgemm3<1,1,1,0,0>, cudaFuncAttributeMaxDynamicSharedMemorySize, GSMEM);
    cudaFuncSetAttribute(hgemm3<1,1,4,1,0>, cudaFuncAttributeMaxDynamicSharedMemorySize, GSMEM);

    float *S;
    __half *img2, *tab2, *w2, *wo2, *qk2, *v2, *fused2;
    int8_t *qk8, *in8, *w8;
    unsigned* rmax;
    cudaGetSymbolAddress((void**)&S,      g_S);
    cudaGetSymbolAddress((void**)&img2,   g_img2);
    cudaGetSymbolAddress((void**)&tab2,   g_tab2);
    cudaGetSymbolAddress((void**)&in8,    g_in8);
    cudaGetSymbolAddress((void**)&w2,     g_w2);
    cudaGetSymbolAddress((void**)&w8,     g_w8);
    cudaGetSymbolAddress((void**)&wo2,    g_wo2);
    cudaGetSymbolAddress((void**)&qk2,    g_qk2);
    cudaGetSymbolAddress((void**)&qk8,    g_qk8);
    cudaGetSymbolAddress((void**)&v2,     g_v2);
    cudaGetSymbolAddress((void**)&rmax,   g_rmax);
    cudaGetSymbolAddress((void**)&fused2, g_fused2);

    const size_t W2SZ = (size_t)DC * 2 * DC;
    __half* wqi2 = w2 + 0 * W2SZ;  __half* wkt2 = w2 + 1 * W2SZ;
    __half* wvt2 = w2 + 2 * W2SZ;  __half* wqt2 = w2 + 3 * W2SZ;
    __half* wki2 = w2 + 4 * W2SZ;  __half* wvi2 = w2 + 5 * W2SZ;
    int8_t* wqi8 = w8 + 0 * W2SZ;  int8_t* wkt8 = w8 + 1 * W2SZ;
    int8_t* wqt8 = w8 + 3 * W2SZ;  int8_t* wki8 = w8 + 4 * W2SZ;
    const size_t QK2 = (size_t)NR * 2 * DC;
    __half* q12 = qk2 + 0 * QK2;   __half* k12 = qk2 + 1 * QK2;
    __half* q22 = qk2 + 2 * QK2;   __half* k22 = qk2 + 3 * QK2;
    int8_t* q18 = qk8 + 0 * QK2;   int8_t* k18 = qk8 + 1 * QK2;
    int8_t* q28 = qk8 + 2 * QK2;   int8_t* k28 = qk8 + 3 * QK2;
    int8_t* img8 = in8;            int8_t* tab8 = in8 + QK2;
    __half* v1r = v2;              __half* v2r = v2 + QK2;
    float*  S_1 = S;               float*  S_2 = S + (size_t)NR * NR;

    // ---- launches 0-2: input conversions + combined weight prep ----
    const size_t tot = (size_t)NR * DC;
    convert_split<<<(unsigned)((tot / 4 + 255) / 256), 256>>>(img, img2, img8, DC, tot);
    convert_split<<<(unsigned)((tot / 4 + 255) / 256), 256>>>(tab, tab2, tab8, DC, tot);
    weight_prep<<<dim3(64, 64, 7), dim3(32, 8)>>>(
        Wqi, Wkt, Wvt, Wqt, Wki, Wvi, Wo,
        wqi2, wkt2, wvt2, wqt2, wki2, wvi2, wo2, w8);

    // ---- launch 3: all 4 Q/K projections (int8 corr + fp16 hi·hi + emit8) ----
    {
        GB4 b = {{ { img2, wqi2, img8, wqi8, bqi, nullptr, q12, q18, nullptr },
                   { tab2, wkt2, tab8, wkt8, bkt, nullptr, k12, k18, nullptr },
                   { tab2, wqt2, tab8, wqt8, bqt, nullptr, q22, q28, nullptr },
                   { img2, wki2, img8, wki8, bki, nullptr, k22, k28, nullptr } }};
        hgemm3<1,1,4,1,0><<<dim3(DC/128, NR/128, 4), TPB, GSMEM>>>(
            b, DC, 2*DC, 2*DC, 2*DC, 2*DC, DC, SCOMB_PROJ);
    }
    // ---- launch 4: both V projections (row-major, 1-pass, per-col bias) ----
    {
        GB4 b = {{ { tab2, wvt2, nullptr, nullptr, bvt, nullptr, v1r, nullptr, nullptr },
                   { img2, wvi2, nullptr, nullptr, bvi, nullptr, v2r, nullptr, nullptr },
                   {}, {} }};
        hgemm3<1,1,1,0,0><<<dim3(DC/128, NR/128, 2), TPB, GSMEM>>>(
            b, DC, 2*DC, 2*DC, 0, 2*DC, DC, 0.0f);
    }
    // ---- launch 5: reset rowmax keys (graph-capturable) ----
    cudaMemsetAsync(rmax, 0, 2 * NR * sizeof(unsigned));
    // ---- launch 6: both QK^T (int8 corr + fp16 hi·hi) + exact rowmax ----
    {
        GB4 b = {{ { q12, k12, q18, k18, nullptr, S_1, nullptr, nullptr, rmax },
                   { q22, k22, q28, k28, nullptr, S_2, nullptr, nullptr, rmax + NR },
                   {}, {} }};
        hgemm3<0,0,4,0,1><<<dim3(NR/128, NR/128, 2), TPB, GSMEM>>>(
            b, DC, 2*DC, 2*DC, 2*DC, NR, 0, SCOMB_QK);
    }
    // ---- launch 7: fused sparse softmax + P·V (both branches) ----
    sparse_softmax_pv<<<dim3(NR, 2), 256>>>(S, rmax, v2, fused2);
    // ---- launch 8: output projection (1-pass, fp32 out) ----
    {
        GB4 b = {{ { fused2, wo2, nullptr, nullptr, bo, out, nullptr, nullptr, nullptr },
                   {}, {}, {} }};
        hgemm3<0,1,1,0,0><<<dim3(2*DC/128, NR/128, 1), TPB, GSMEM>>>(
            b, 2*DC, 4*DC, 4*DC, 0, 2*DC, 0, 0.0f);
    }
}

// round 17
// speedup vs baseline: 1.4314x; 1.1260x over previous
#include <cuda_runtime.h>
#include <cuda_fp16.h>
#include <cstdint>

#define NR 8192
#define DC 1024
#define PCAP 1024                    // sparse candidate capacity per row
#define SMARGIN 21.0f                // logit threshold below exact row max

// int8 scales (validated R10-R16)
#define S8_HI 32.0f
#define S8_LO 65536.0f
#define SCOMB_QK   (1.0f / 2097152.0f)     // 2^-21
#define SIN_HI 16.0f
#define SIN_LO 16384.0f
#define SW_HI  1024.0f
#define SW_LO  1048576.0f
#define SCOMB_PROJ (1.0f / 16777216.0f)    // 2^-24

// ---------------------------------------------------------------------------
// Static device scratch. Split-fp16 tensors stored [rows, 2K]: hi | lo.
// ---------------------------------------------------------------------------
__device__ float    g_S[(size_t)2 * NR * NR];           // logits (branch 0/1)
__device__ __half   g_img2[(size_t)NR * 2 * DC];
__device__ __half   g_tab2[(size_t)NR * 2 * DC];
__device__ int8_t   g_in8[(size_t)2 * NR * 2 * DC];     // img8, tab8 (hi|lo)
__device__ __half   g_w2[(size_t)6 * DC * 2 * DC];      // 6x W^T [1024,2048]
__device__ int8_t   g_w8[(size_t)6 * DC * 2 * DC];      // 6x W^T int8 (hi|lo)
__device__ __half   g_wo2[(size_t)2 * DC * 4 * DC];     // Wo^T [2048,4096]
__device__ __half   g_qk2[(size_t)4 * NR * 2 * DC];     // q1,k1,q2,k2 fp16 hi|lo
__device__ int8_t   g_qk8[(size_t)4 * NR * 2 * DC];     // q1,k1,q2,k2 int8 hi|lo
__device__ __half   g_v2[(size_t)2 * NR * 2 * DC];      // v1,v2 row-major hi|lo
__device__ unsigned g_rmax[2 * NR];                     // ordered-uint row maxes
__device__ __half   g_fused2[(size_t)NR * 4 * DC];

// ---------------------------------------------------------------------------
// helpers
// ---------------------------------------------------------------------------
__device__ __forceinline__ uint32_t smem_u32(const void* p) {
    uint32_t a;
    asm("{ .reg .u64 t; cvta.to.shared.u64 t, %1; cvt.u32.u64 %0, t; }" : "=r"(a) : "l"(p));
    return a;
}
__device__ __forceinline__ void cp16(uint32_t d, const void* g) {
    asm volatile("cp.async.cg.shared.global [%0], [%1], 16;"
                 :: "r"(d), "l"(__cvta_generic_to_global(g)) : "memory");
}
__device__ __forceinline__ void ldm4(uint32_t* r, uint32_t a) {
    asm volatile("ldmatrix.sync.aligned.m8n8.x4.shared.b16 {%0,%1,%2,%3}, [%4];"
                 : "=r"(r[0]), "=r"(r[1]), "=r"(r[2]), "=r"(r[3]) : "r"(a));
}
__device__ __forceinline__ void mma16816(float* d, const uint32_t* a, const uint32_t* b) {
    asm("mma.sync.aligned.m16n8k16.row.col.f32.f16.f16.f32 "
        "{%0,%1,%2,%3}, {%4,%5,%6,%7}, {%8,%9}, {%0,%1,%2,%3};"
        : "+f"(d[0]), "+f"(d[1]), "+f"(d[2]), "+f"(d[3])
        : "r"(a[0]), "r"(a[1]), "r"(a[2]), "r"(a[3]), "r"(b[0]), "r"(b[1]));
}
__device__ __forceinline__ void mma16832s8(int* d, const uint32_t* a, const uint32_t* b) {
    asm("mma.sync.aligned.m16n8k32.row.col.s32.s8.s8.s32 "
        "{%0,%1,%2,%3}, {%4,%5,%6,%7}, {%8,%9}, {%0,%1,%2,%3};"
        : "+r"(d[0]), "+r"(d[1]), "+r"(d[2]), "+r"(d[3])
        : "r"(a[0]), "r"(a[1]), "r"(a[2]), "r"(a[3]), "r"(b[0]), "r"(b[1]));
}
__device__ __forceinline__ __half2 split_hi(float x0, float x1, __half2& lo) {
    __half h0 = __float2half_rn(x0), h1 = __float2half_rn(x1);
    lo = __halves2half2(__float2half_rn(x0 - __half2float(h0)),
                        __float2half_rn(x1 - __half2float(h1)));
    return __halves2half2(h0, h1);
}
__device__ __forceinline__ int8_t q8clamp(float x, float s) {
    int v = __float2int_rn(x * s);
    v = v > 127 ? 127 : (v < -127 ? -127 : v);
    return (int8_t)v;
}
// ordered-uint encoding for float atomicMax (monotone; key(x) > 0 for all finite x)
__device__ __forceinline__ unsigned fkey(float x) {
    unsigned b = __float_as_uint(x);
    return (b & 0x80000000u) ? ~b : (b | 0x80000000u);
}
__device__ __forceinline__ float fdec(unsigned u) {
    return (u & 0x80000000u) ? __uint_as_float(u ^ 0x80000000u) : __uint_as_float(~u);
}

// ---------------------------------------------------------------------------
// Batched split NT GEMM (validated core):  C = A . B^T per blockIdx.z
// PASSES=4: int8 corrections (2 sweeps: Ahi·Blo, Alo·Bhi) + fp16 hi·hi
// PASSES=5: int8 correction (1 sweep: Ahi·Blo only) + fp16 hi·hi
// PASSES=1: hi·hi only.  RMAX=1: epilogue also atomicMax's per-row maxes.
// ---------------------------------------------------------------------------
#define TPB 256
#define AST 144
#define STG (128 * AST * 2)
#define GSMEM (3 * STG)

struct GB { const __half* A; const __half* B; const int8_t* A8; const int8_t* B8;
            const float* bias; float* Cf; __half* Ch; int8_t* C8; unsigned* rmax; };
struct GB4 { GB g[4]; };

template <int OUT_MODE, int BIAS, int PASSES, int EMIT8, int RMAX>
__global__ __launch_bounds__(TPB, 2)
void hgemm3(const __grid_constant__ GB4 batch, int K,
            size_t ldA, size_t ldB, size_t ld8, int ldc, int lo_off, float s_comb)
{
    extern __shared__ char smc[];
    const uint32_t sb = smem_u32(smc);
    const GB gb = batch.g[blockIdx.z];
    const int tid = threadIdx.x;
    const int wid = tid >> 5, lane = tid & 31;
    const int g = lane >> 2, t = lane & 3;
    const int wm = wid & 1, wn = wid >> 1;
    const int m0 = blockIdx.y * 128, n0 = blockIdx.x * 128;

    const int K64 = K >> 6;
    const int corr  = (PASSES == 4) ? K64 : ((PASSES == 5) ? (K >> 7) : 0);
    const int total = corr + K64;

    const int lr = tid >> 3;
    const int lc  = (tid & 7) * 8;
    const int lcB = (tid & 7) * 16;

    auto load_stage = [&](int s, int step) {
        if (step < total) {
            const uint32_t da = sb + s * STG + lr * AST + lcB;
            const uint32_t db = da + 128 * AST;
            if ((PASSES == 4 || PASSES == 5) && step < corr) {
                int a8o, b8o, kk;
                if (PASSES == 5) {            // single sweep: Ahi8 . Blo8
                    a8o = 0; b8o = K; kk = step;
                } else {
                    const int spw = K >> 7;
                    const int swp = step / spw;
                    kk = step - swp * spw;
                    a8o = swp ? K : 0;
                    b8o = swp ? 0 : K;
                }
                const int8_t* ga  = gb.A8 + (size_t)(m0 + lr) * ld8 + a8o + kk * 128 + lcB;
                const int8_t* gbp = gb.B8 + (size_t)(n0 + lr) * ld8 + b8o + kk * 128 + lcB;
#pragma unroll
                for (int i = 0; i < 4; ++i) {
                    cp16(da + i * 32 * AST, ga  + (size_t)i * 32 * ld8);
                    cp16(db + i * 32 * AST, gbp + (size_t)i * 32 * ld8);
                }
            } else {
                const int kk = step - corr;
                const __half* ga  = gb.A + (size_t)(m0 + lr) * ldA + (size_t)kk * 64 + lc;
                const __half* gbp = gb.B + (size_t)(n0 + lr) * ldB + (size_t)kk * 64 + lc;
#pragma unroll
                for (int i = 0; i < 4; ++i) {
                    cp16(da + i * 32 * AST, ga  + (size_t)i * 32 * ldA);
                    cp16(db + i * 32 * AST, gbp + (size_t)i * 32 * ldB);
                }
            }
        }
        asm volatile("cp.async.commit_group;" ::: "memory");
    };

    const uint32_t aoff = (uint32_t)(wm * 64 + (lane & 15)) * AST + ((lane >> 4) << 4);
    const uint32_t boff = 128 * AST +
        (uint32_t)(wn * 32 + ((lane & 7) | ((lane >> 1) & 8))) * AST +
        (((lane >> 3) & 1) << 4);

    load_stage(0, 0);
    load_stage(1, 1);

    int iacc[4][4][4];
    if (PASSES == 4 || PASSES == 5) {
#pragma unroll
        for (int i = 0; i < 4; ++i)
#pragma unroll
            for (int j = 0; j < 4; ++j)
#pragma unroll
                for (int r = 0; r < 4; ++r) iacc[i][j][r] = 0;
    }

    for (int step = 0; step < corr; ++step) {
        asm volatile("cp.async.wait_group 1;" ::: "memory");
        __syncthreads();
        load_stage((step + 2) % 3, step + 2);
        const uint32_t sbase = sb + (step % 3) * STG;
#pragma unroll
        for (int kh = 0; kh < 4; ++kh) {
            const uint32_t ko = kh * 32;
            uint32_t af[4][4], bf[4][2];
#pragma unroll
            for (int mt = 0; mt < 4; ++mt)
                ldm4(af[mt], sbase + aoff + (uint32_t)mt * 16 * AST + ko);
#pragma unroll
            for (int np = 0; np < 2; ++np) {
                uint32_t r[4];
                ldm4(r, sbase + boff + (uint32_t)np * 16 * AST + ko);
                bf[np * 2][0] = r[0];      bf[np * 2][1] = r[1];
                bf[np * 2 + 1][0] = r[2];  bf[np * 2 + 1][1] = r[3];
            }
#pragma unroll
            for (int mt = 0; mt < 4; ++mt)
#pragma unroll
                for (int nt = 0; nt < 4; ++nt)
                    mma16832s8(iacc[mt][nt], af[mt], bf[nt]);
        }
    }

    float acc[4][4][4];
#pragma unroll
    for (int i = 0; i < 4; ++i)
#pragma unroll
        for (int j = 0; j < 4; ++j) {
            if (PASSES == 4 || PASSES == 5) {
#pragma unroll
                for (int r = 0; r < 4; ++r)
                    acc[i][j][r] = (float)iacc[i][j][r] * s_comb;
            } else {
#pragma unroll
                for (int r = 0; r < 4; ++r) acc[i][j][r] = 0.0f;
            }
        }

    for (int step = corr; step < total; ++step) {
        asm volatile("cp.async.wait_group 1;" ::: "memory");
        __syncthreads();
        load_stage((step + 2) % 3, step + 2);
        const uint32_t sbase = sb + (step % 3) * STG;
#pragma unroll
        for (int kh = 0; kh < 4; ++kh) {
            const uint32_t ko = kh * 32;
            uint32_t af[4][4], bf[4][2];
#pragma unroll
            for (int mt = 0; mt < 4; ++mt)
                ldm4(af[mt], sbase + aoff + (uint32_t)mt * 16 * AST + ko);
#pragma unroll
            for (int np = 0; np < 2; ++np) {
                uint32_t r[4];
                ldm4(r, sbase + boff + (uint32_t)np * 16 * AST + ko);
                bf[np * 2][0] = r[0];      bf[np * 2][1] = r[1];
                bf[np * 2 + 1][0] = r[2];  bf[np * 2 + 1][1] = r[3];
            }
#pragma unroll
            for (int mt = 0; mt < 4; ++mt)
#pragma unroll
                for (int nt = 0; nt < 4; ++nt)
                    mma16816(acc[mt][nt], af[mt], bf[nt]);
        }
    }

    // ---- rowmax smem init (RMAX mode; stage smem no longer read) ----
    unsigned* rm = reinterpret_cast<unsigned*>(smc);
    if (RMAX) {
        __syncthreads();
        if (tid < 128) rm[tid] = 0u;
        __syncthreads();
    }

    // ---- epilogue ----
#pragma unroll
    for (int mt = 0; mt < 4; ++mt) {
        const int r0 = m0 + wm * 64 + mt * 16 + g;
        const int r1 = r0 + 8;
#pragma unroll
        for (int nt = 0; nt < 4; ++nt) {
            const int col = n0 + wn * 32 + nt * 8 + 2 * t;
            float v00 = acc[mt][nt][0], v01 = acc[mt][nt][1];
            float v10 = acc[mt][nt][2], v11 = acc[mt][nt][3];
            if (BIAS == 1) {
                const float b0 = gb.bias[col], b1 = gb.bias[col + 1];
                v00 += b0; v01 += b1; v10 += b0; v11 += b1;
            } else if (BIAS == 2) {
                const float b0 = gb.bias[r0], b1 = gb.bias[r1];
                v00 += b0; v01 += b0; v10 += b1; v11 += b1;
            }
            if (OUT_MODE == 0) {
                *reinterpret_cast<float2*>(&gb.Cf[(size_t)r0 * ldc + col]) = make_float2(v00, v01);
                *reinterpret_cast<float2*>(&gb.Cf[(size_t)r1 * ldc + col]) = make_float2(v10, v11);
                if (RMAX) {
                    atomicMax(&rm[wm * 64 + mt * 16 + g],     fkey(fmaxf(v00, v01)));
                    atomicMax(&rm[wm * 64 + mt * 16 + g + 8], fkey(fmaxf(v10, v11)));
                }
            } else {
                __half2 lo0, lo1;
                __half2 hi0 = split_hi(v00, v01, lo0);
                __half2 hi1 = split_hi(v10, v11, lo1);
                __half2* p0 = reinterpret_cast<__half2*>(&gb.Ch[(size_t)r0 * ldc + col]);
                __half2* p1 = reinterpret_cast<__half2*>(&gb.Ch[(size_t)r1 * ldc + col]);
                p0[0] = hi0;  p0[lo_off / 2] = lo0;
                p1[0] = hi1;  p1[lo_off / 2] = lo1;
                if (EMIT8) {
                    const float l00 = __low2float(lo0), l01 = __high2float(lo0);
                    const float l10 = __low2float(lo1), l11 = __high2float(lo1);
                    char2 h8a = { q8clamp(v00, S8_HI), q8clamp(v01, S8_HI) };
                    char2 h8b = { q8clamp(v10, S8_HI), q8clamp(v11, S8_HI) };
                    char2 l8a = { q8clamp(l00, S8_LO), q8clamp(l01, S8_LO) };
                    char2 l8b = { q8clamp(l10, S8_LO), q8clamp(l11, S8_LO) };
                    *reinterpret_cast<char2*>(&gb.C8[(size_t)r0 * ldc + col])          = h8a;
                    *reinterpret_cast<char2*>(&gb.C8[(size_t)r1 * ldc + col])          = h8b;
                    *reinterpret_cast<char2*>(&gb.C8[(size_t)r0 * ldc + lo_off + col]) = l8a;
                    *reinterpret_cast<char2*>(&gb.C8[(size_t)r1 * ldc + lo_off + col]) = l8b;
                }
            }
        }
    }

    if (RMAX) {
        __syncthreads();
        if (tid < 128) atomicMax(&gb.rmax[m0 + tid], rm[tid]);
    }
}

// ---------------------------------------------------------------------------
// fp32 [R,C] -> split fp16 [R,2C] + int8 [R,2C]
// ---------------------------------------------------------------------------
__global__ __launch_bounds__(256)
void convert_split(const float* __restrict__ in, __half* __restrict__ out,
                   int8_t* __restrict__ out8, int C, size_t total)
{
    size_t i = ((size_t)blockIdx.x * 256 + threadIdx.x) * 4;
    if (i >= total) return;
    float4 v = *reinterpret_cast<const float4*>(&in[i]);
    size_t r = i / C;
    int c = (int)(i - r * C);
    __half2 lo0, lo1;
    __half2 hi0 = split_hi(v.x, v.y, lo0);
    __half2 hi1 = split_hi(v.z, v.w, lo1);
    __half* row = out + r * (2 * (size_t)C);
    *reinterpret_cast<__half2*>(&row[c])         = hi0;
    *reinterpret_cast<__half2*>(&row[c + 2])     = hi1;
    *reinterpret_cast<__half2*>(&row[C + c])     = lo0;
    *reinterpret_cast<__half2*>(&row[C + c + 2]) = lo1;
    int8_t* row8 = out8 + r * (2 * (size_t)C);
    char4 h8 = { q8clamp(__low2float(hi0), SIN_HI), q8clamp(__high2float(hi0), SIN_HI),
                 q8clamp(__low2float(hi1), SIN_HI), q8clamp(__high2float(hi1), SIN_HI) };
    char4 l8 = { q8clamp(__low2float(lo0), SIN_LO), q8clamp(__high2float(lo0), SIN_LO),
                 q8clamp(__low2float(lo1), SIN_LO), q8clamp(__high2float(lo1), SIN_LO) };
    *reinterpret_cast<char4*>(&row8[c])     = h8;
    *reinterpret_cast<char4*>(&row8[C + c]) = l8;
}

// ---------------------------------------------------------------------------
// All 7 weight transposes in ONE launch (+ int8 for projection weights)
// ---------------------------------------------------------------------------
__global__ __launch_bounds__(256)
void weight_prep(const float* w0, const float* w1, const float* w2c,
                 const float* w3, const float* w4, const float* w5,
                 const float* w6,
                 __half* o0, __half* o1, __half* o2, __half* o3,
                 __half* o4, __half* o5, __half* o6, int8_t* o8base)
{
    const float* src; __half* dst; int R, C;
    switch (blockIdx.z) {
        case 0: src = w0; dst = o0; R = DC; C = DC; break;
        case 1: src = w1; dst = o1; R = DC; C = DC; break;
        case 2: src = w2c; dst = o2; R = DC; C = DC; break;
        case 3: src = w3; dst = o3; R = DC; C = DC; break;
        case 4: src = w4; dst = o4; R = DC; C = DC; break;
        case 5: src = w5; dst = o5; R = DC; C = DC; break;
        default: src = w6; dst = o6; R = 2 * DC; C = 2 * DC; break;
    }
    const int bx = blockIdx.x * 32, by = blockIdx.y * 32;
    if (bx >= C || by >= R) return;
    int8_t* dst8 = (blockIdx.z < 6)
        ? o8base + (size_t)blockIdx.z * DC * 2 * DC : nullptr;

    __shared__ float tl[32][33];
    const int tx = threadIdx.x, ty = threadIdx.y;
#pragma unroll
    for (int j = ty; j < 32; j += 8)
        tl[j][tx] = src[(size_t)(by + j) * C + bx + tx];
    __syncthreads();
#pragma unroll
    for (int j = ty; j < 32; j += 8) {
        const float v = tl[tx][j];
        const __half h = __float2half_rn(v);
        const float hf = __half2float(h);
        const __half l = __float2half_rn(v - hf);
        __half* row = dst + (size_t)(bx + j) * (2 * (size_t)R);
        row[by + tx]     = h;
        row[R + by + tx] = l;
        if (dst8) {
            int8_t* row8 = dst8 + (size_t)(bx + j) * (2 * (size_t)R);
            row8[by + tx]     = q8clamp(hf, SW_HI);
            row8[R + by + tx] = q8clamp(__half2float(l), SW_LO);
        }
    }
}

// ---------------------------------------------------------------------------
// Fused sparse softmax + P·V (validated R16). One block per (row, branch).
// ---------------------------------------------------------------------------
__global__ __launch_bounds__(256)
void sparse_softmax_pv(const float* __restrict__ S,
                       const unsigned* __restrict__ rmax,
                       const __half* __restrict__ v2,
                       __half* __restrict__ fused2)
{
    __shared__ int   lidx[PCAP];
    __shared__ float lp[PCAP];
    __shared__ float red[256];
    __shared__ int   wtot[8];
    __shared__ int   ltot;
    __shared__ int   chunk_tot;
    __shared__ float s_inv;

    const int rowi = blockIdx.x, br = blockIdx.y;
    const int tid = threadIdx.x;
    const int lane = tid & 31, wrp = tid >> 5;
    const float* p = S + (size_t)br * NR * NR + (size_t)rowi * NR;
    const float bmax = fdec(rmax[br * NR + rowi]);
    const float thr = bmax - SMARGIN;
    if (tid == 0) ltot = 0;
    __syncthreads();

    for (int base = 0; base < NR; base += 1024) {
        float4 v = *reinterpret_cast<const float4*>(&p[base + tid * 4]);
        float pe[4] = { v.x, v.y, v.z, v.w };
        const int c = (pe[0] > thr) + (pe[1] > thr) + (pe[2] > thr) + (pe[3] > thr);
        int pre = c;
#pragma unroll
        for (int s = 1; s < 32; s <<= 1) {
            int n = __shfl_up_sync(0xffffffffu, pre, s);
            if (lane >= s) pre += n;
        }
        if (lane == 31) wtot[wrp] = pre;
        __syncthreads();
        if (tid == 0) {
            int r = 0;
#pragma unroll
            for (int w = 0; w < 8; ++w) { const int t2 = wtot[w]; wtot[w] = r; r += t2; }
            chunk_tot = r;
        }
        __syncthreads();
        int o = ltot + wtot[wrp] + pre - c;
#pragma unroll
        for (int e = 0; e < 4; ++e) {
            if (pe[e] > thr) {
                if (o < PCAP) { lidx[o] = base + tid * 4 + e; lp[o] = pe[e]; }
                ++o;
            }
        }
        __syncthreads();
        if (tid == 0) ltot += chunk_tot;
        __syncthreads();
    }
    const int cnt = ltot < PCAP ? ltot : PCAP;

    float lsum = 0.0f;
    for (int i = tid; i < cnt; i += 256) {
        const float e = __expf(lp[i] - bmax);
        lp[i] = e;
        lsum += e;
    }
    red[tid] = lsum;
    __syncthreads();
#pragma unroll
    for (int s = 128; s > 0; s >>= 1) {
        if (tid < s) red[tid] += red[tid + s];
        __syncthreads();
    }
    if (tid == 0) s_inv = 1.0f / red[0];
    __syncthreads();
    const float inv = s_inv;
    for (int i = tid; i < cnt; i += 256) lp[i] *= inv;
    __syncthreads();

    const __half* V = v2 + (size_t)br * NR * 2 * DC;
    const int d = tid * 4;
    float a0 = 0.f, a1 = 0.f, a2 = 0.f, a3 = 0.f;
#pragma unroll 4
    for (int j = 0; j < cnt; ++j) {
        const float pj = lp[j];
        const float2 hv = *reinterpret_cast<const float2*>(
            V + (size_t)lidx[j] * (2 * DC) + d);
        const __half2* hh = reinterpret_cast<const __half2*>(&hv);
        a0 = fmaf(pj, __low2float(hh[0]), a0);
        a1 = fmaf(pj, __high2float(hh[0]), a1);
        a2 = fmaf(pj, __low2float(hh[1]), a2);
        a3 = fmaf(pj, __high2float(hh[1]), a3);
    }

    const int col = (br == 0 ? DC : 0) + d;
    __half2 lo0, lo1;
    __half2 hi0 = split_hi(a0, a1, lo0);
    __half2 hi1 = split_hi(a2, a3, lo1);
    __half* frow = fused2 + (size_t)rowi * 4 * DC;
    *reinterpret_cast<__half2*>(&frow[col])              = hi0;
    *reinterpret_cast<__half2*>(&frow[col + 2])          = hi1;
    *reinterpret_cast<__half2*>(&frow[2 * DC + col])     = lo0;
    *reinterpret_cast<__half2*>(&frow[2 * DC + col + 2]) = lo1;
}

// ---------------------------------------------------------------------------
// Launch sequence
// ---------------------------------------------------------------------------
extern "C" void kernel_launch(void* const* d_in, const int* in_sizes, int n_in,
                              void* d_out, int out_size)
{
    const float* img = (const float*)d_in[0];
    const float* tab = (const float*)d_in[1];
    const float* Wqi = (const float*)d_in[2];  const float* bqi = (const float*)d_in[3];
    const float* Wkt = (const float*)d_in[4];  const float* bkt = (const float*)d_in[5];
    const float* Wvt = (const float*)d_in[6];  const float* bvt = (const float*)d_in[7];
    const float* Wqt = (const float*)d_in[8];  const float* bqt = (const float*)d_in[9];
    const float* Wki = (const float*)d_in[10]; const float* bki = (const float*)d_in[11];
    const float* Wvi = (const float*)d_in[12]; const float* bvi = (const float*)d_in[13];
    const float* Wo  = (const float*)d_in[14]; const float* bo  = (const float*)d_in[15];
    float* out = (float*)d_out;

    cudaFuncSetAttribute(hgemm3<0,0,5,0,1>, cudaFuncAttributeMaxDynamicSharedMemorySize, GSMEM);
    cudaFuncSetAttribute(hgemm3<0,1,1,0,0>, cudaFuncAttributeMaxDynamicSharedMemorySize, GSMEM);
    cudaFuncSetAttribute(hgemm3<1,1,1,0,0>, cudaFuncAttributeMaxDynamicSharedMemorySize, GSMEM);
    cudaFuncSetAttribute(hgemm3<1,1,4,1,0>, cudaFuncAttributeMaxDynamicSharedMemorySize, GSMEM);

    float *S;
    __half *img2, *tab2, *w2, *wo2, *qk2, *v2, *fused2;
    int8_t *qk8, *in8, *w8;
    unsigned* rmax;
    cudaGetSymbolAddress((void**)&S,      g_S);
    cudaGetSymbolAddress((void**)&img2,   g_img2);
    cudaGetSymbolAddress((void**)&tab2,   g_tab2);
    cudaGetSymbolAddress((void**)&in8,    g_in8);
    cudaGetSymbolAddress((void**)&w2,     g_w2);
    cudaGetSymbolAddress((void**)&w8,     g_w8);
    cudaGetSymbolAddress((void**)&wo2,    g_wo2);
    cudaGetSymbolAddress((void**)&qk2,    g_qk2);
    cudaGetSymbolAddress((void**)&qk8,    g_qk8);
    cudaGetSymbolAddress((void**)&v2,     g_v2);
    cudaGetSymbolAddress((void**)&rmax,   g_rmax);
    cudaGetSymbolAddress((void**)&fused2, g_fused2);

    const size_t W2SZ = (size_t)DC * 2 * DC;
    __half* wqi2 = w2 + 0 * W2SZ;  __half* wkt2 = w2 + 1 * W2SZ;
    __half* wvt2 = w2 + 2 * W2SZ;  __half* wqt2 = w2 + 3 * W2SZ;
    __half* wki2 = w2 + 4 * W2SZ;  __half* wvi2 = w2 + 5 * W2SZ;
    int8_t* wqi8 = w8 + 0 * W2SZ;  int8_t* wkt8 = w8 + 1 * W2SZ;
    int8_t* wqt8 = w8 + 3 * W2SZ;  int8_t* wki8 = w8 + 4 * W2SZ;
    const size_t QK2 = (size_t)NR * 2 * DC;
    __half* q12 = qk2 + 0 * QK2;   __half* k12 = qk2 + 1 * QK2;
    __half* q22 = qk2 + 2 * QK2;   __half* k22 = qk2 + 3 * QK2;
    int8_t* q18 = qk8 + 0 * QK2;   int8_t* k18 = qk8 + 1 * QK2;
    int8_t* q28 = qk8 + 2 * QK2;   int8_t* k28 = qk8 + 3 * QK2;
    int8_t* img8 = in8;            int8_t* tab8 = in8 + QK2;
    __half* v1r = v2;              __half* v2r = v2 + QK2;
    float*  S_1 = S;               float*  S_2 = S + (size_t)NR * NR;

    // ---- launches 0-2: input conversions + combined weight prep ----
    const size_t tot = (size_t)NR * DC;
    convert_split<<<(unsigned)((tot / 4 + 255) / 256), 256>>>(img, img2, img8, DC, tot);
    convert_split<<<(unsigned)((tot / 4 + 255) / 256), 256>>>(tab, tab2, tab8, DC, tot);
    weight_prep<<<dim3(64, 64, 7), dim3(32, 8)>>>(
        Wqi, Wkt, Wvt, Wqt, Wki, Wvi, Wo,
        wqi2, wkt2, wvt2, wqt2, wki2, wvi2, wo2, w8);

    // ---- launch 3: all 4 Q/K projections (2-sweep int8 corr + fp16 + emit8) ----
    {
        GB4 b = {{ { img2, wqi2, img8, wqi8, bqi, nullptr, q12, q18, nullptr },
                   { tab2, wkt2, tab8, wkt8, bkt, nullptr, k12, k18, nullptr },
                   { tab2, wqt2, tab8, wqt8, bqt, nullptr, q22, q28, nullptr },
                   { img2, wki2, img8, wki8, bki, nullptr, k22, k28, nullptr } }};
        hgemm3<1,1,4,1,0><<<dim3(DC/128, NR/128, 4), TPB, GSMEM>>>(
            b, DC, 2*DC, 2*DC, 2*DC, 2*DC, DC, SCOMB_PROJ);
    }
    // ---- launch 4: both V projections (row-major, 1-pass, per-col bias) ----
    {
        GB4 b = {{ { tab2, wvt2, nullptr, nullptr, bvt, nullptr, v1r, nullptr, nullptr },
                   { img2, wvi2, nullptr, nullptr, bvi, nullptr, v2r, nullptr, nullptr },
                   {}, {} }};
        hgemm3<1,1,1,0,0><<<dim3(DC/128, NR/128, 2), TPB, GSMEM>>>(
            b, DC, 2*DC, 2*DC, 0, 2*DC, DC, 0.0f);
    }
    // ---- launch 5: reset rowmax keys (graph-capturable) ----
    cudaMemsetAsync(rmax, 0, 2 * NR * sizeof(unsigned));
    // ---- launch 6: both QK^T (1-sweep int8 corr + fp16 hi·hi) + exact rowmax ----
    {
        GB4 b = {{ { q12, k12, q18, k18, nullptr, S_1, nullptr, nullptr, rmax },
                   { q22, k22, q28, k28, nullptr, S_2, nullptr, nullptr, rmax + NR },
                   {}, {} }};
        hgemm3<0,0,5,0,1><<<dim3(NR/128, NR/128, 2), TPB, GSMEM>>>(
            b, DC, 2*DC, 2*DC, 2*DC, NR, 0, SCOMB_QK);
    }
    // ---- launch 7: fused sparse softmax + P·V (both branches) ----
    sparse_softmax_pv<<<dim3(NR, 2), 256>>>(S, rmax, v2, fused2);
    // ---- launch 8: output projection (1-pass, fp32 out) ----
    {
        GB4 b = {{ { fused2, wo2, nullptr, nullptr, bo, out, nullptr, nullptr, nullptr },
                   {}, {}, {} }};
        hgemm3<0,1,1,0,0><<<dim3(2*DC/128, NR/128, 1), TPB, GSMEM>>>(
            b, 2*DC, 4*DC, 4*DC, 0, 2*DC, 0, 0.0f);
    }
}